// round 4
// baseline (speedup 1.0000x reference)
#include <cuda_runtime.h>

// Problem constants (fixed shapes from the reference)
#define BB   2
#define NN   50000
#define FF   16
#define EE   1600000
#define EH   32      // hidden
#define EOUT 30      // second layer out (padded to 32 internally)
#define NOUT 16      // final out per node

__device__ __forceinline__ float sigmoidf_(float x) {
    return __fdividef(1.0f, 1.0f + __expf(-x));
}

__device__ __forceinline__ void red_add4(float* p, float a, float b, float c, float d) {
    asm volatile("red.global.add.v4.f32 [%0], {%1,%2,%3,%4};"
                 :: "l"(p), "f"(a), "f"(b), "f"(c), "f"(d) : "memory");
}

__global__ void zero_kernel(float4* __restrict__ out, int n4) {
    int i = blockIdx.x * blockDim.x + threadIdx.x;
    if (i < n4) out[i] = make_float4(0.f, 0.f, 0.f, 0.f);
}

// One thread per (edge, batch). Computes the 33->32->30 sigmoid MLP, folds W3
// (30->16) into the edge, and scatters +/-g into d_out with vector reds.
__global__ __launch_bounds__(256) void edge_kernel(
    const float* __restrict__ nf,          // (B, N, F)
    const float* __restrict__ ew,          // (B, E)
    const int*   __restrict__ eidx,        // (2, E) int32 (or int64 -- probed)
    const float* __restrict__ W1,          // (33, 32)
    const float* __restrict__ b1,          // (32)
    const float* __restrict__ W2,          // (32, 30)
    const float* __restrict__ b2,          // (30)
    const float* __restrict__ W3,          // (30, 16)
    float* __restrict__ out)               // (B, N, 16) accumulator
{
    __shared__ __align__(16) float sW1[33 * 32];   // row-major [k][j]
    __shared__ __align__(16) float sW2[32 * 32];   // padded cols 30..31 = 0
    __shared__ __align__(16) float sW3[32 * 16];   // padded rows 30..31 = 0
    __shared__ __align__(16) float sb1[32];
    __shared__ __align__(16) float sb2[32];        // padded = 0 (harmless: W3 pad rows are 0)
    __shared__ int s_is64;                         // dtype probe result

    const int t = threadIdx.x;
    for (int i = t; i < 33 * 32; i += 256) sW1[i] = W1[i];
    for (int i = t; i < 32 * 32; i += 256) {
        int k = i >> 5, j = i & 31;
        sW2[i] = (j < EOUT) ? W2[k * EOUT + j] : 0.0f;
    }
    for (int i = t; i < 32 * 16; i += 256) {
        int k = i >> 4, j = i & 15;
        sW3[i] = (k < EOUT) ? W3[k * 16 + j] : 0.0f;
    }
    if (t < 32) sb1[t] = b1[t];
    if (t < 32) sb2[t] = (t < EOUT) ? b2[t] : 0.0f;
    if (t == 0) {
        // If the index buffer is int64 (little-endian, values < 2^31), all odd
        // int32 words are 0. With int32 random indices the odds of this are ~0.
        s_is64 = (eidx[1] == 0 && eidx[3] == 0 && eidx[5] == 0 && eidx[7] == 0);
    }
    __syncthreads();

    const int e = blockIdx.x * 256 + t;
    if (e >= EE) return;
    const int b = blockIdx.y;

    int src, tgt;
    if (s_is64) {
        src = eidx[2 * (size_t)e];                 // low word of int64
        tgt = eidx[2 * ((size_t)EE + e)];
    } else {
        src = eidx[e];
        tgt = eidx[EE + e];
    }

    const float4* __restrict__ xs = (const float4*)(nf + ((size_t)b * NN + src) * FF);
    const float4* __restrict__ xt = (const float4*)(nf + ((size_t)b * NN + tgt) * FF);
    const float   w = __ldg(ew + (size_t)b * EE + e);

    const float4* W1v = (const float4*)sW1;   // row k = W1v[k*8 + r]
    const float4* W2v = (const float4*)sW2;   // row k = W2v[k*8 + r]
    const float4* W3v = (const float4*)sW3;   // row k = W3v[k*4 + r]

    // ---- layer 1: h1 = sigmoid(x @ W1 + b1), x = [src_feats | tgt_feats | w] ----
    float h1[32];
    {
        const float4* bv = (const float4*)sb1;
        #pragma unroll
        for (int q = 0; q < 8; q++) {
            float4 v = bv[q];
            h1[4*q+0] = v.x; h1[4*q+1] = v.y; h1[4*q+2] = v.z; h1[4*q+3] = v.w;
        }
    }
    #pragma unroll
    for (int q = 0; q < 4; q++) {
        float4 v = xs[q];
        float xv[4] = {v.x, v.y, v.z, v.w};
        #pragma unroll
        for (int kk = 0; kk < 4; kk++) {
            const int k = 4 * q + kk;
            #pragma unroll
            for (int r = 0; r < 8; r++) {
                float4 wv = W1v[k * 8 + r];
                h1[4*r+0] = fmaf(xv[kk], wv.x, h1[4*r+0]);
                h1[4*r+1] = fmaf(xv[kk], wv.y, h1[4*r+1]);
                h1[4*r+2] = fmaf(xv[kk], wv.z, h1[4*r+2]);
                h1[4*r+3] = fmaf(xv[kk], wv.w, h1[4*r+3]);
            }
        }
    }
    #pragma unroll
    for (int q = 0; q < 4; q++) {
        float4 v = xt[q];
        float xv[4] = {v.x, v.y, v.z, v.w};
        #pragma unroll
        for (int kk = 0; kk < 4; kk++) {
            const int k = 16 + 4 * q + kk;
            #pragma unroll
            for (int r = 0; r < 8; r++) {
                float4 wv = W1v[k * 8 + r];
                h1[4*r+0] = fmaf(xv[kk], wv.x, h1[4*r+0]);
                h1[4*r+1] = fmaf(xv[kk], wv.y, h1[4*r+1]);
                h1[4*r+2] = fmaf(xv[kk], wv.z, h1[4*r+2]);
                h1[4*r+3] = fmaf(xv[kk], wv.w, h1[4*r+3]);
            }
        }
    }
    #pragma unroll
    for (int r = 0; r < 8; r++) {
        float4 wv = W1v[32 * 8 + r];
        h1[4*r+0] = fmaf(w, wv.x, h1[4*r+0]);
        h1[4*r+1] = fmaf(w, wv.y, h1[4*r+1]);
        h1[4*r+2] = fmaf(w, wv.z, h1[4*r+2]);
        h1[4*r+3] = fmaf(w, wv.w, h1[4*r+3]);
    }
    #pragma unroll
    for (int j = 0; j < 32; j++) h1[j] = sigmoidf_(h1[j]);

    // ---- layer 2: h2 = sigmoid(h1 @ W2 + b2) (padded to 32) ----
    float h2[32];
    {
        const float4* bv = (const float4*)sb2;
        #pragma unroll
        for (int q = 0; q < 8; q++) {
            float4 v = bv[q];
            h2[4*q+0] = v.x; h2[4*q+1] = v.y; h2[4*q+2] = v.z; h2[4*q+3] = v.w;
        }
    }
    #pragma unroll
    for (int k = 0; k < 32; k++) {
        const float a = h1[k];
        #pragma unroll
        for (int r = 0; r < 8; r++) {
            float4 wv = W2v[k * 8 + r];
            h2[4*r+0] = fmaf(a, wv.x, h2[4*r+0]);
            h2[4*r+1] = fmaf(a, wv.y, h2[4*r+1]);
            h2[4*r+2] = fmaf(a, wv.z, h2[4*r+2]);
            h2[4*r+3] = fmaf(a, wv.w, h2[4*r+3]);
        }
    }
    #pragma unroll
    for (int j = 0; j < 32; j++) h2[j] = sigmoidf_(h2[j]);
    // h2[30], h2[31] = sigmoid(0) = 0.5, but W3 pad rows are 0 -> no effect.

    // ---- layer 3 folded: g = h2 @ W3 (16 floats) ----
    float g[16];
    #pragma unroll
    for (int j = 0; j < 16; j++) g[j] = 0.0f;
    #pragma unroll
    for (int k = 0; k < 32; k++) {
        const float a = h2[k];
        #pragma unroll
        for (int r = 0; r < 4; r++) {
            float4 wv = W3v[k * 4 + r];
            g[4*r+0] = fmaf(a, wv.x, g[4*r+0]);
            g[4*r+1] = fmaf(a, wv.y, g[4*r+1]);
            g[4*r+2] = fmaf(a, wv.z, g[4*r+2]);
            g[4*r+3] = fmaf(a, wv.w, g[4*r+3]);
        }
    }

    // ---- scatter: out[b, tgt] += g, out[b, src] -= g ----
    float* pt = out + ((size_t)b * NN + tgt) * NOUT;
    float* ps = out + ((size_t)b * NN + src) * NOUT;
    #pragma unroll
    for (int r = 0; r < 4; r++)
        red_add4(pt + 4 * r, g[4*r+0], g[4*r+1], g[4*r+2], g[4*r+3]);
    #pragma unroll
    for (int r = 0; r < 4; r++)
        red_add4(ps + 4 * r, -g[4*r+0], -g[4*r+1], -g[4*r+2], -g[4*r+3]);
}

__global__ void finalize_kernel(float* __restrict__ out,
                                const float* __restrict__ b3, int n) {
    int i = blockIdx.x * blockDim.x + threadIdx.x;
    if (i < n) {
        float v = out[i] + __ldg(b3 + (i & 15));
        out[i] = sigmoidf_(v);
    }
}

extern "C" void kernel_launch(void* const* d_in, const int* in_sizes, int n_in,
                              void* d_out, int out_size) {
    const float* nf   = (const float*)d_in[0];      // node_features (B,N,F)
    const float* ew   = (const float*)d_in[1];      // edge_weight   (B,E)
    const int*   eidx = (const int*)d_in[2];        // edge_index    (2,E)
    const float* W1   = (const float*)d_in[3];
    const float* b1   = (const float*)d_in[4];
    const float* W2   = (const float*)d_in[5];
    const float* b2   = (const float*)d_in[6];
    const float* W3   = (const float*)d_in[7];
    const float* b3   = (const float*)d_in[8];
    float* out = (float*)d_out;

    const int total = BB * NN * NOUT;  // 1,600,000 floats = 400,000 float4
    const int n4 = total / 4;

    zero_kernel<<<(n4 + 255) / 256, 256>>>((float4*)out, n4);

    dim3 grid((EE + 255) / 256, BB);
    edge_kernel<<<grid, 256>>>(nf, ew, eidx, W1, b1, W2, b2, W3, out);

    finalize_kernel<<<(total + 255) / 256, 256>>>(out, b3, total);
}

// round 5
// speedup vs baseline: 1.0509x; 1.0509x over previous
#include <cuda_runtime.h>

// Problem constants (fixed shapes from the reference)
#define BB   2
#define NN   50000
#define FF   16
#define EE   1600000
#define EH   32      // hidden
#define EOUT 30      // second layer out (padded to 32 internally)
#define NOUT 16      // final out per node

typedef unsigned long long ull;

// ---- packed f32x2 helpers (SASS FFMA2/FADD2 path, sm_100+) ----
__device__ __forceinline__ ull pack2(float lo, float hi) {
    ull r;
    asm("mov.b64 %0, {%1, %2};" : "=l"(r) : "f"(lo), "f"(hi));
    return r;
}
__device__ __forceinline__ void unpack2(ull p, float& lo, float& hi) {
    asm("mov.b64 {%0, %1}, %2;" : "=f"(lo), "=f"(hi) : "l"(p));
}
__device__ __forceinline__ ull fma2(ull a, ull b, ull c) {
    ull d;
    asm("fma.rn.f32x2 %0, %1, %2, %3;" : "=l"(d) : "l"(a), "l"(b), "l"(c));
    return d;
}
__device__ __forceinline__ ull add2(ull a, ull b) {
    ull d;
    asm("add.rn.f32x2 %0, %1, %2;" : "=l"(d) : "l"(a), "l"(b));
    return d;
}

__device__ __forceinline__ float sigmoidf_(float x) {
    return __fdividef(1.0f, 1.0f + __expf(-x));
}
__device__ __forceinline__ ull sigmoid2_(ull p) {
    float lo, hi;
    unpack2(p, lo, hi);
    return pack2(sigmoidf_(lo), sigmoidf_(hi));
}

__device__ __forceinline__ void red_add4(float* p, float a, float b, float c, float d) {
    asm volatile("red.global.add.v4.f32 [%0], {%1,%2,%3,%4};"
                 :: "l"(p), "f"(a), "f"(b), "f"(c), "f"(d) : "memory");
}

// Scratch: per-node layer-1 partials, batch-pair packed.
// g_A[n][j] = (x[b0,n]@W1[0:16,j] + b1[j],  x[b1,n]@W1[0:16,j] + b1[j])
// g_B[n][j] = (x[b0,n]@W1[16:32,j],         x[b1,n]@W1[16:32,j])
__device__ __align__(16) ull g_A[NN * EH];   // 12.8 MB
__device__ __align__(16) ull g_B[NN * EH];   // 12.8 MB

__global__ void zero_kernel(float4* __restrict__ out, int n4) {
    int i = blockIdx.x * blockDim.x + threadIdx.x;
    if (i < n4) out[i] = make_float4(0.f, 0.f, 0.f, 0.f);
}

// One thread per node: builds the packed A/B tables (both batches at once).
__global__ __launch_bounds__(128) void node_kernel(
    const float* __restrict__ nf,    // (B, N, F)
    const float* __restrict__ W1,    // (33, 32)
    const float* __restrict__ b1)    // (32)
{
    __shared__ __align__(16) ull sW1p[32 * 32];   // rows 0..31 broadcast-packed
    __shared__ __align__(16) ull sb1p[32];

    const int t = threadIdx.x;
    for (int i = t; i < 32 * 32; i += 128) {
        float v = W1[i];
        sW1p[i] = pack2(v, v);
    }
    if (t < 32) { float v = b1[t]; sb1p[t] = pack2(v, v); }
    __syncthreads();

    const int n = blockIdx.x * 128 + t;
    if (n >= NN) return;

    // pack node features of both batches: xp[k] = (x[b0][k], x[b1][k])
    const float4* x0 = (const float4*)(nf + (size_t)n * FF);
    const float4* x1 = (const float4*)(nf + ((size_t)NN + n) * FF);
    ull xp[16];
    #pragma unroll
    for (int q = 0; q < 4; q++) {
        float4 a = x0[q], b = x1[q];
        xp[4*q+0] = pack2(a.x, b.x);
        xp[4*q+1] = pack2(a.y, b.y);
        xp[4*q+2] = pack2(a.z, b.z);
        xp[4*q+3] = pack2(a.w, b.w);
    }

    // A = x @ W1[0:16] + b1
    {
        ull acc[32];
        #pragma unroll
        for (int j = 0; j < 32; j++) acc[j] = sb1p[j];
        #pragma unroll
        for (int k = 0; k < 16; k++) {
            const ull xk = xp[k];
            #pragma unroll
            for (int j = 0; j < 32; j++)
                acc[j] = fma2(xk, sW1p[k * 32 + j], acc[j]);
        }
        ulonglong2* dst = (ulonglong2*)(g_A + (size_t)n * EH);
        #pragma unroll
        for (int q = 0; q < 16; q++) dst[q] = make_ulonglong2(acc[2*q], acc[2*q+1]);
    }
    // B = x @ W1[16:32]
    {
        ull acc[32];
        #pragma unroll
        for (int j = 0; j < 32; j++) acc[j] = 0ull;  // packed (0.f, 0.f)
        #pragma unroll
        for (int k = 0; k < 16; k++) {
            const ull xk = xp[k];
            #pragma unroll
            for (int j = 0; j < 32; j++)
                acc[j] = fma2(xk, sW1p[(16 + k) * 32 + j], acc[j]);
        }
        ulonglong2* dst = (ulonglong2*)(g_B + (size_t)n * EH);
        #pragma unroll
        for (int q = 0; q < 16; q++) dst[q] = make_ulonglong2(acc[2*q], acc[2*q+1]);
    }
}

// One thread per edge, both batches packed as f32x2 lanes.
__global__ __launch_bounds__(128) void edge_kernel(
    const float* __restrict__ ew,          // (B, E)
    const int*   __restrict__ eidx,        // (2, E) int32 (or int64 -- probed)
    const float* __restrict__ W1,          // (33, 32) -- only row 32 used here
    const float* __restrict__ W2,          // (32, 30)
    const float* __restrict__ b2,          // (30)
    const float* __restrict__ W3,          // (30, 16)
    float* __restrict__ out)               // (B, N, 16) accumulator
{
    __shared__ __align__(16) ull sW2p[32 * 32];   // [k][j], cols 30..31 zero
    __shared__ __align__(16) ull sW3p[32 * 16];   // [k][j], rows 30..31 zero
    __shared__ __align__(16) ull sW1Lp[32];       // W1 row 32 (edge-weight row)
    __shared__ __align__(16) ull sb2p[32];        // padded zero
    __shared__ int s_is64;

    const int t = threadIdx.x;
    for (int i = t; i < 32 * 32; i += 128) {
        int k = i >> 5, j = i & 31;
        float v = (j < EOUT) ? W2[k * EOUT + j] : 0.0f;
        sW2p[i] = pack2(v, v);
    }
    for (int i = t; i < 32 * 16; i += 128) {
        int k = i >> 4, j = i & 15;
        float v = (k < EOUT) ? W3[k * 16 + j] : 0.0f;
        sW3p[i] = pack2(v, v);
    }
    if (t < 32) { float v = W1[32 * 32 + t]; sW1Lp[t] = pack2(v, v); }
    if (t < 32) { float v = (t < EOUT) ? b2[t] : 0.0f; sb2p[t] = pack2(v, v); }
    if (t == 0) {
        // int64 probe: little-endian int64 (<2^31) => odd int32 words are 0.
        s_is64 = (eidx[1] == 0 && eidx[3] == 0 && eidx[5] == 0 && eidx[7] == 0);
    }
    __syncthreads();

    const int e = blockIdx.x * 128 + t;
    if (e >= EE) return;

    int src, tgt;
    if (s_is64) {
        src = eidx[2 * (size_t)e];
        tgt = eidx[2 * ((size_t)EE + e)];
    } else {
        src = eidx[e];
        tgt = eidx[EE + e];
    }

    const ull wp = pack2(__ldg(ew + e), __ldg(ew + (size_t)EE + e));

    // ---- layer 1: h1 = sigmoid(A[src] + B[tgt] + w * W1_last) ----
    const ulonglong2* pa = (const ulonglong2*)(g_A + (size_t)src * EH);
    const ulonglong2* pb = (const ulonglong2*)(g_B + (size_t)tgt * EH);
    ull h1[32];
    #pragma unroll
    for (int q = 0; q < 16; q++) {
        ulonglong2 a = pa[q];
        ulonglong2 b = pb[q];
        h1[2*q+0] = add2(a.x, b.x);
        h1[2*q+1] = add2(a.y, b.y);
    }
    #pragma unroll
    for (int j = 0; j < 32; j++)
        h1[j] = sigmoid2_(fma2(wp, sW1Lp[j], h1[j]));

    // ---- layer 2: h2 = sigmoid(h1 @ W2 + b2) ----
    ull h2[32];
    #pragma unroll
    for (int j = 0; j < 32; j++) h2[j] = sb2p[j];
    #pragma unroll
    for (int k = 0; k < 32; k++) {
        const ull a = h1[k];
        #pragma unroll
        for (int j = 0; j < 32; j++)
            h2[j] = fma2(a, sW2p[k * 32 + j], h2[j]);
    }
    #pragma unroll
    for (int j = 0; j < 32; j++) h2[j] = sigmoid2_(h2[j]);
    // pads: sigmoid(0)=0.5 but W3 pad rows are zero -> no effect.

    // ---- layer 3 folded: g = h2 @ W3 ----
    ull g[16];
    #pragma unroll
    for (int j = 0; j < 16; j++) g[j] = 0ull;
    #pragma unroll
    for (int k = 0; k < 32; k++) {
        const ull a = h2[k];
        #pragma unroll
        for (int j = 0; j < 16; j++)
            g[j] = fma2(a, sW3p[k * 16 + j], g[j]);
    }

    // ---- scatter: out[b, tgt] += g_b, out[b, src] -= g_b, both batches ----
    float lo[16], hi[16];
    #pragma unroll
    for (int j = 0; j < 16; j++) unpack2(g[j], lo[j], hi[j]);

    float* pt0 = out + (size_t)tgt * NOUT;
    float* ps0 = out + (size_t)src * NOUT;
    float* pt1 = out + ((size_t)NN + tgt) * NOUT;
    float* ps1 = out + ((size_t)NN + src) * NOUT;
    #pragma unroll
    for (int r = 0; r < 4; r++) {
        red_add4(pt0 + 4*r,  lo[4*r+0],  lo[4*r+1],  lo[4*r+2],  lo[4*r+3]);
        red_add4(pt1 + 4*r,  hi[4*r+0],  hi[4*r+1],  hi[4*r+2],  hi[4*r+3]);
    }
    #pragma unroll
    for (int r = 0; r < 4; r++) {
        red_add4(ps0 + 4*r, -lo[4*r+0], -lo[4*r+1], -lo[4*r+2], -lo[4*r+3]);
        red_add4(ps1 + 4*r, -hi[4*r+0], -hi[4*r+1], -hi[4*r+2], -hi[4*r+3]);
    }
}

__global__ void finalize_kernel(float* __restrict__ out,
                                const float* __restrict__ b3, int n) {
    int i = blockIdx.x * blockDim.x + threadIdx.x;
    if (i < n) {
        float v = out[i] + __ldg(b3 + (i & 15));
        out[i] = sigmoidf_(v);
    }
}

extern "C" void kernel_launch(void* const* d_in, const int* in_sizes, int n_in,
                              void* d_out, int out_size) {
    const float* nf   = (const float*)d_in[0];      // node_features (B,N,F)
    const float* ew   = (const float*)d_in[1];      // edge_weight   (B,E)
    const int*   eidx = (const int*)d_in[2];        // edge_index    (2,E)
    const float* W1   = (const float*)d_in[3];
    const float* b1   = (const float*)d_in[4];
    const float* W2   = (const float*)d_in[5];
    const float* b2   = (const float*)d_in[6];
    const float* W3   = (const float*)d_in[7];
    const float* b3   = (const float*)d_in[8];
    float* out = (float*)d_out;

    const int total = BB * NN * NOUT;  // 1,600,000 floats
    const int n4 = total / 4;

    zero_kernel<<<(n4 + 255) / 256, 256>>>((float4*)out, n4);
    node_kernel<<<(NN + 127) / 128, 128>>>(nf, W1, b1);
    edge_kernel<<<EE / 128, 128>>>(ew, eidx, W1, W2, b2, W3, out);
    finalize_kernel<<<(total + 255) / 256, 256>>>(out, b3, total);
}

// round 6
// speedup vs baseline: 1.1431x; 1.0877x over previous
#include <cuda_runtime.h>

// Problem constants (fixed shapes from the reference)
#define BB   2
#define NN   50000
#define FF   16
#define EE   1600000
#define EH   32      // hidden
#define EOUT 30      // second layer out (padded to 32 internally)
#define NOUT 16      // final out per node

__device__ __forceinline__ float sigmoidf_(float x) {
    return __fdividef(1.0f, 1.0f + __expf(-x));
}

__device__ __forceinline__ void red_add4(float* p, float a, float b, float c, float d) {
    asm volatile("red.global.add.v4.f32 [%0], {%1,%2,%3,%4};"
                 :: "l"(p), "f"(a), "f"(b), "f"(c), "f"(d) : "memory");
}

// Per-node, per-batch layer-1 partials (scalar fp32):
// g_A[(b*NN+n)*32 + j] = x[b,n] @ W1[0:16, j] + b1[j]
// g_B[(b*NN+n)*32 + j] = x[b,n] @ W1[16:32, j]
__device__ __align__(16) float g_A[BB * NN * EH];   // 12.8 MB
__device__ __align__(16) float g_B[BB * NN * EH];   // 12.8 MB

__global__ void zero_kernel(float4* __restrict__ out, int n4) {
    int i = blockIdx.x * blockDim.x + threadIdx.x;
    if (i < n4) out[i] = make_float4(0.f, 0.f, 0.f, 0.f);
}

// One thread per (node, batch): builds A/B tables.
__global__ __launch_bounds__(128) void node_kernel(
    const float* __restrict__ nf,    // (B, N, F)
    const float* __restrict__ W1,    // (33, 32)
    const float* __restrict__ b1)    // (32)
{
    __shared__ __align__(16) float sW1[32 * 32];  // rows 0..31 (node-feature rows)
    __shared__ __align__(16) float sb1[32];

    const int t = threadIdx.x;
    for (int i = t; i < 32 * 32; i += 128) sW1[i] = W1[i];
    if (t < 32) sb1[t] = b1[t];
    __syncthreads();

    const int idx = blockIdx.x * 128 + t;          // 0 .. BB*NN-1
    if (idx >= BB * NN) return;

    const float4* xv = (const float4*)(nf + (size_t)idx * FF);
    float x[16];
    #pragma unroll
    for (int q = 0; q < 4; q++) {
        float4 v = xv[q];
        x[4*q+0] = v.x; x[4*q+1] = v.y; x[4*q+2] = v.z; x[4*q+3] = v.w;
    }

    float accA[32], accB[32];
    #pragma unroll
    for (int j = 0; j < 32; j++) { accA[j] = sb1[j]; accB[j] = 0.0f; }
    #pragma unroll
    for (int k = 0; k < 16; k++) {
        const float xa = x[k];
        #pragma unroll
        for (int j = 0; j < 32; j++) {
            accA[j] = fmaf(xa, sW1[k * 32 + j], accA[j]);
            accB[j] = fmaf(xa, sW1[(16 + k) * 32 + j], accB[j]);
        }
    }
    float4* da = (float4*)(g_A + (size_t)idx * EH);
    float4* db = (float4*)(g_B + (size_t)idx * EH);
    #pragma unroll
    for (int q = 0; q < 8; q++) {
        da[q] = make_float4(accA[4*q+0], accA[4*q+1], accA[4*q+2], accA[4*q+3]);
        db[q] = make_float4(accB[4*q+0], accB[4*q+1], accB[4*q+2], accB[4*q+3]);
    }
}

// One thread per (edge, batch): layer1 via gathered tables, then L2/L3, scatter.
__global__ __launch_bounds__(256) void edge_kernel(
    const float* __restrict__ ew,          // (B, E)
    const int*   __restrict__ eidx,        // (2, E) int32 (or int64 -- probed)
    const float* __restrict__ W1,          // (33, 32) -- only row 32 used here
    const float* __restrict__ W2,          // (32, 30)
    const float* __restrict__ b2,          // (30)
    const float* __restrict__ W3,          // (30, 16)
    float* __restrict__ out)               // (B, N, 16) accumulator
{
    __shared__ __align__(16) float sW2[32 * 32];  // [k][j], cols 30..31 zero
    __shared__ __align__(16) float sW3[32 * 16];  // [k][j], rows 30..31 zero
    __shared__ __align__(16) float sW1L[32];      // W1 row 32 (edge-weight row)
    __shared__ __align__(16) float sb2[32];       // padded zero
    __shared__ int s_is64;

    const int t = threadIdx.x;
    for (int i = t; i < 32 * 32; i += 256) {
        int k = i >> 5, j = i & 31;
        sW2[i] = (j < EOUT) ? W2[k * EOUT + j] : 0.0f;
    }
    for (int i = t; i < 32 * 16; i += 256) {
        int k = i >> 4, j = i & 15;
        sW3[i] = (k < EOUT) ? W3[k * 16 + j] : 0.0f;
    }
    if (t < 32) sW1L[t] = W1[32 * 32 + t];
    if (t < 32) sb2[t] = (t < EOUT) ? b2[t] : 0.0f;
    if (t == 0) {
        // int64 probe: little-endian int64 (<2^31) => odd int32 words are 0.
        s_is64 = (eidx[1] == 0 && eidx[3] == 0 && eidx[5] == 0 && eidx[7] == 0);
    }
    __syncthreads();

    const int e = blockIdx.x * 256 + t;
    if (e >= EE) return;
    const int b = blockIdx.y;

    int src, tgt;
    if (s_is64) {
        src = eidx[2 * (size_t)e];
        tgt = eidx[2 * ((size_t)EE + e)];
    } else {
        src = eidx[e];
        tgt = eidx[EE + e];
    }

    const float w = __ldg(ew + (size_t)b * EE + e);

    // ---- layer 1: h1 = sigmoid(A[b,src] + B[b,tgt] + w * W1_last) ----
    const float4* pa = (const float4*)(g_A + ((size_t)b * NN + src) * EH);
    const float4* pb = (const float4*)(g_B + ((size_t)b * NN + tgt) * EH);
    float h1[32];
    #pragma unroll
    for (int q = 0; q < 8; q++) {
        float4 a = pa[q];
        float4 c = pb[q];
        h1[4*q+0] = a.x + c.x;
        h1[4*q+1] = a.y + c.y;
        h1[4*q+2] = a.z + c.z;
        h1[4*q+3] = a.w + c.w;
    }
    #pragma unroll
    for (int j = 0; j < 32; j++)
        h1[j] = sigmoidf_(fmaf(w, sW1L[j], h1[j]));

    // ---- layer 2: h2 = sigmoid(h1 @ W2 + b2) (padded to 32) ----
    const float4* W2v = (const float4*)sW2;
    float h2[32];
    {
        const float4* bv = (const float4*)sb2;
        #pragma unroll
        for (int q = 0; q < 8; q++) {
            float4 v = bv[q];
            h2[4*q+0] = v.x; h2[4*q+1] = v.y; h2[4*q+2] = v.z; h2[4*q+3] = v.w;
        }
    }
    #pragma unroll
    for (int k = 0; k < 32; k++) {
        const float a = h1[k];
        #pragma unroll
        for (int r = 0; r < 8; r++) {
            float4 wv = W2v[k * 8 + r];
            h2[4*r+0] = fmaf(a, wv.x, h2[4*r+0]);
            h2[4*r+1] = fmaf(a, wv.y, h2[4*r+1]);
            h2[4*r+2] = fmaf(a, wv.z, h2[4*r+2]);
            h2[4*r+3] = fmaf(a, wv.w, h2[4*r+3]);
        }
    }
    #pragma unroll
    for (int j = 0; j < 32; j++) h2[j] = sigmoidf_(h2[j]);
    // pads: sigmoid(0)=0.5 but W3 pad rows are zero -> no effect.

    // ---- layer 3 folded: g = h2 @ W3 ----
    const float4* W3v = (const float4*)sW3;
    float g[16];
    #pragma unroll
    for (int j = 0; j < 16; j++) g[j] = 0.0f;
    #pragma unroll
    for (int k = 0; k < 32; k++) {
        const float a = h2[k];
        #pragma unroll
        for (int r = 0; r < 4; r++) {
            float4 wv = W3v[k * 4 + r];
            g[4*r+0] = fmaf(a, wv.x, g[4*r+0]);
            g[4*r+1] = fmaf(a, wv.y, g[4*r+1]);
            g[4*r+2] = fmaf(a, wv.z, g[4*r+2]);
            g[4*r+3] = fmaf(a, wv.w, g[4*r+3]);
        }
    }

    // ---- scatter: out[b, tgt] += g, out[b, src] -= g ----
    float* pt = out + ((size_t)b * NN + tgt) * NOUT;
    float* ps = out + ((size_t)b * NN + src) * NOUT;
    #pragma unroll
    for (int r = 0; r < 4; r++)
        red_add4(pt + 4 * r, g[4*r+0], g[4*r+1], g[4*r+2], g[4*r+3]);
    #pragma unroll
    for (int r = 0; r < 4; r++)
        red_add4(ps + 4 * r, -g[4*r+0], -g[4*r+1], -g[4*r+2], -g[4*r+3]);
}

__global__ void finalize_kernel(float* __restrict__ out,
                                const float* __restrict__ b3, int n) {
    int i = blockIdx.x * blockDim.x + threadIdx.x;
    if (i < n) {
        float v = out[i] + __ldg(b3 + (i & 15));
        out[i] = sigmoidf_(v);
    }
}

extern "C" void kernel_launch(void* const* d_in, const int* in_sizes, int n_in,
                              void* d_out, int out_size) {
    const float* nf   = (const float*)d_in[0];      // node_features (B,N,F)
    const float* ew   = (const float*)d_in[1];      // edge_weight   (B,E)
    const int*   eidx = (const int*)d_in[2];        // edge_index    (2,E)
    const float* W1   = (const float*)d_in[3];
    const float* b1   = (const float*)d_in[4];
    const float* W2   = (const float*)d_in[5];
    const float* b2   = (const float*)d_in[6];
    const float* W3   = (const float*)d_in[7];
    const float* b3   = (const float*)d_in[8];
    float* out = (float*)d_out;

    const int total = BB * NN * NOUT;  // 1,600,000 floats
    const int n4 = total / 4;

    zero_kernel<<<(n4 + 255) / 256, 256>>>((float4*)out, n4);
    node_kernel<<<(BB * NN + 127) / 128, 128>>>(nf, W1, b1);

    dim3 grid((EE + 255) / 256, BB);
    edge_kernel<<<grid, 256>>>(ew, eidx, W1, W2, b2, W3, out);

    finalize_kernel<<<(total + 255) / 256, 256>>>(out, b3, total);
}

// round 7
// speedup vs baseline: 1.3868x; 1.2132x over previous
#include <cuda_runtime.h>

// Problem constants (fixed shapes from the reference)
#define BB   2
#define NN   50000
#define FF   16
#define EE   1600000
#define EH   32      // hidden
#define EOUT 30      // second layer out (padded to 32 internally)
#define NOUT 16      // final out per node

__device__ __forceinline__ float sigmoidf_(float x) {
    return __fdividef(1.0f, 1.0f + __expf(-x));
}

__device__ __forceinline__ void red_add4(float* p, float a, float b, float c, float d) {
    asm volatile("red.global.add.v4.f32 [%0], {%1,%2,%3,%4};"
                 :: "l"(p), "f"(a), "f"(b), "f"(c), "f"(d) : "memory");
}

// Per-node, per-batch layer-1 partials (scalar fp32), 128B-aligned rows:
// g_A[(b*NN+n)*32 + j] = x[b,n] @ W1[0:16, j] + b1[j]
// g_B[(b*NN+n)*32 + j] = x[b,n] @ W1[16:32, j]
__device__ __align__(128) float g_A[BB * NN * EH];   // 12.8 MB
__device__ __align__(128) float g_B[BB * NN * EH];   // 12.8 MB

__global__ void zero_kernel(float4* __restrict__ out, int n4) {
    int i = blockIdx.x * blockDim.x + threadIdx.x;
    if (i < n4) out[i] = make_float4(0.f, 0.f, 0.f, 0.f);
}

// One thread per (node, batch): builds A/B tables.
__global__ __launch_bounds__(128) void node_kernel(
    const float* __restrict__ nf,    // (B, N, F)
    const float* __restrict__ W1,    // (33, 32)
    const float* __restrict__ b1)    // (32)
{
    __shared__ __align__(16) float sW1[32 * 32];  // rows 0..31 (node-feature rows)
    __shared__ __align__(16) float sb1[32];

    const int t = threadIdx.x;
    for (int i = t; i < 32 * 32; i += 128) sW1[i] = W1[i];
    if (t < 32) sb1[t] = b1[t];
    __syncthreads();

    const int idx = blockIdx.x * 128 + t;          // 0 .. BB*NN-1
    if (idx >= BB * NN) return;

    const float4* xv = (const float4*)(nf + (size_t)idx * FF);
    float x[16];
    #pragma unroll
    for (int q = 0; q < 4; q++) {
        float4 v = xv[q];
        x[4*q+0] = v.x; x[4*q+1] = v.y; x[4*q+2] = v.z; x[4*q+3] = v.w;
    }

    float accA[32], accB[32];
    #pragma unroll
    for (int j = 0; j < 32; j++) { accA[j] = sb1[j]; accB[j] = 0.0f; }
    #pragma unroll
    for (int k = 0; k < 16; k++) {
        const float xa = x[k];
        #pragma unroll
        for (int j = 0; j < 32; j++) {
            accA[j] = fmaf(xa, sW1[k * 32 + j], accA[j]);
            accB[j] = fmaf(xa, sW1[(16 + k) * 32 + j], accB[j]);
        }
    }
    float4* da = (float4*)(g_A + (size_t)idx * EH);
    float4* db = (float4*)(g_B + (size_t)idx * EH);
    #pragma unroll
    for (int q = 0; q < 8; q++) {
        da[q] = make_float4(accA[4*q+0], accA[4*q+1], accA[4*q+2], accA[4*q+3]);
        db[q] = make_float4(accB[4*q+0], accB[4*q+1], accB[4*q+2], accB[4*q+3]);
    }
}

// One thread per (edge, batch); warp-cooperative coalesced table gather.
// Block = 128 threads (4 warps). EE % 128 == 0 -> all warps full.
#define SLOT_F 36   // floats per staging slot (144 B): row 128B + 16B pad
__global__ __launch_bounds__(128) void edge_kernel(
    const float* __restrict__ ew,          // (B, E)
    const int*   __restrict__ eidx,        // (2, E) int32 (or int64 -- probed)
    const float* __restrict__ W1,          // (33, 32) -- only row 32 used here
    const float* __restrict__ W2,          // (32, 30)
    const float* __restrict__ b2,          // (30)
    const float* __restrict__ W3,          // (30, 16)
    float* __restrict__ out)               // (B, N, 16) accumulator
{
    __shared__ __align__(16) float sW2[32 * 32];  // [k][j], cols 30..31 zero
    __shared__ __align__(16) float sW3[32 * 16];  // [k][j], rows 30..31 zero
    __shared__ __align__(16) float sW1L[32];      // W1 row 32 (edge-weight row)
    __shared__ __align__(16) float sb2[32];       // padded zero
    __shared__ __align__(16) float stage[4][32 * SLOT_F];  // per-warp row staging
    __shared__ int s_is64;

    const int t = threadIdx.x;
    for (int i = t; i < 32 * 32; i += 128) {
        int k = i >> 5, j = i & 31;
        sW2[i] = (j < EOUT) ? W2[k * EOUT + j] : 0.0f;
    }
    for (int i = t; i < 32 * 16; i += 128) {
        int k = i >> 4, j = i & 15;
        sW3[i] = (k < EOUT) ? W3[k * 16 + j] : 0.0f;
    }
    if (t < 32) sW1L[t] = W1[32 * 32 + t];
    if (t < 32) sb2[t] = (t < EOUT) ? b2[t] : 0.0f;
    if (t == 0) {
        // int64 probe: little-endian int64 (<2^31) => odd int32 words are 0.
        s_is64 = (eidx[1] == 0 && eidx[3] == 0 && eidx[5] == 0 && eidx[7] == 0);
    }
    __syncthreads();

    const int wid  = t >> 5;
    const int lane = t & 31;
    const int e = blockIdx.x * 128 + t;
    const int b = blockIdx.y;

    int src, tgt;
    if (s_is64) {
        src = eidx[2 * (size_t)e];
        tgt = eidx[2 * ((size_t)EE + e)];
    } else {
        src = eidx[e];
        tgt = eidx[EE + e];
    }

    const float w = __ldg(ew + (size_t)b * EE + e);

    float* buf = stage[wid];
    const int chunk = lane & 7;   // which 16B chunk of a row
    const int sub   = lane >> 3;  // which of 4 rows this round

    float h1[32];

    // ---- stage A rows (coalesced: 8 lanes cover one 128B row) ----
    {
        const float* baseA = g_A + (size_t)b * NN * EH;
        #pragma unroll
        for (int i = 0; i < 8; i++) {
            const int eo  = i * 4 + sub;                       // edge-in-warp
            const int row = __shfl_sync(0xffffffffu, src, eo);
            const float4 v = *(const float4*)(baseA + (size_t)row * EH + chunk * 4);
            *(float4*)(buf + eo * SLOT_F + chunk * 4) = v;
        }
        __syncwarp();
        const float4* r = (const float4*)(buf + lane * SLOT_F);
        #pragma unroll
        for (int q = 0; q < 8; q++) {
            float4 v = r[q];
            h1[4*q+0] = v.x; h1[4*q+1] = v.y; h1[4*q+2] = v.z; h1[4*q+3] = v.w;
        }
        __syncwarp();   // done reading before B pass overwrites
    }
    // ---- stage B rows ----
    {
        const float* baseB = g_B + (size_t)b * NN * EH;
        #pragma unroll
        for (int i = 0; i < 8; i++) {
            const int eo  = i * 4 + sub;
            const int row = __shfl_sync(0xffffffffu, tgt, eo);
            const float4 v = *(const float4*)(baseB + (size_t)row * EH + chunk * 4);
            *(float4*)(buf + eo * SLOT_F + chunk * 4) = v;
        }
        __syncwarp();
        const float4* r = (const float4*)(buf + lane * SLOT_F);
        #pragma unroll
        for (int q = 0; q < 8; q++) {
            float4 v = r[q];
            h1[4*q+0] += v.x; h1[4*q+1] += v.y; h1[4*q+2] += v.z; h1[4*q+3] += v.w;
        }
    }

    // ---- layer 1 activation: h1 = sigmoid(h1 + w * W1_last) ----
    #pragma unroll
    for (int j = 0; j < 32; j++)
        h1[j] = sigmoidf_(fmaf(w, sW1L[j], h1[j]));

    // ---- layer 2: h2 = sigmoid(h1 @ W2 + b2) (padded to 32) ----
    const float4* W2v = (const float4*)sW2;
    float h2[32];
    {
        const float4* bv = (const float4*)sb2;
        #pragma unroll
        for (int q = 0; q < 8; q++) {
            float4 v = bv[q];
            h2[4*q+0] = v.x; h2[4*q+1] = v.y; h2[4*q+2] = v.z; h2[4*q+3] = v.w;
        }
    }
    #pragma unroll
    for (int k = 0; k < 32; k++) {
        const float a = h1[k];
        #pragma unroll
        for (int r = 0; r < 8; r++) {
            float4 wv = W2v[k * 8 + r];
            h2[4*r+0] = fmaf(a, wv.x, h2[4*r+0]);
            h2[4*r+1] = fmaf(a, wv.y, h2[4*r+1]);
            h2[4*r+2] = fmaf(a, wv.z, h2[4*r+2]);
            h2[4*r+3] = fmaf(a, wv.w, h2[4*r+3]);
        }
    }
    #pragma unroll
    for (int j = 0; j < 32; j++) h2[j] = sigmoidf_(h2[j]);
    // pads: sigmoid(0)=0.5 but W3 pad rows are zero -> no effect.

    // ---- layer 3 folded: g = h2 @ W3 ----
    const float4* W3v = (const float4*)sW3;
    float g[16];
    #pragma unroll
    for (int j = 0; j < 16; j++) g[j] = 0.0f;
    #pragma unroll
    for (int k = 0; k < 32; k++) {
        const float a = h2[k];
        #pragma unroll
        for (int r = 0; r < 4; r++) {
            float4 wv = W3v[k * 4 + r];
            g[4*r+0] = fmaf(a, wv.x, g[4*r+0]);
            g[4*r+1] = fmaf(a, wv.y, g[4*r+1]);
            g[4*r+2] = fmaf(a, wv.z, g[4*r+2]);
            g[4*r+3] = fmaf(a, wv.w, g[4*r+3]);
        }
    }

    // ---- scatter: out[b, tgt] += g, out[b, src] -= g ----
    float* pt = out + ((size_t)b * NN + tgt) * NOUT;
    float* ps = out + ((size_t)b * NN + src) * NOUT;
    #pragma unroll
    for (int r = 0; r < 4; r++)
        red_add4(pt + 4 * r, g[4*r+0], g[4*r+1], g[4*r+2], g[4*r+3]);
    #pragma unroll
    for (int r = 0; r < 4; r++)
        red_add4(ps + 4 * r, -g[4*r+0], -g[4*r+1], -g[4*r+2], -g[4*r+3]);
}

__global__ void finalize_kernel(float* __restrict__ out,
                                const float* __restrict__ b3, int n) {
    int i = blockIdx.x * blockDim.x + threadIdx.x;
    if (i < n) {
        float v = out[i] + __ldg(b3 + (i & 15));
        out[i] = sigmoidf_(v);
    }
}

extern "C" void kernel_launch(void* const* d_in, const int* in_sizes, int n_in,
                              void* d_out, int out_size) {
    const float* nf   = (const float*)d_in[0];      // node_features (B,N,F)
    const float* ew   = (const float*)d_in[1];      // edge_weight   (B,E)
    const int*   eidx = (const int*)d_in[2];        // edge_index    (2,E)
    const float* W1   = (const float*)d_in[3];
    const float* b1   = (const float*)d_in[4];
    const float* W2   = (const float*)d_in[5];
    const float* b2   = (const float*)d_in[6];
    const float* W3   = (const float*)d_in[7];
    const float* b3   = (const float*)d_in[8];
    float* out = (float*)d_out;

    const int total = BB * NN * NOUT;  // 1,600,000 floats
    const int n4 = total / 4;

    zero_kernel<<<(n4 + 255) / 256, 256>>>((float4*)out, n4);
    node_kernel<<<(BB * NN + 127) / 128, 128>>>(nf, W1, b1);

    dim3 grid(EE / 128, BB);   // EE % 128 == 0 -> all warps full
    edge_kernel<<<grid, 128>>>(ew, eidx, W1, W2, b2, W3, out);

    finalize_kernel<<<(total + 255) / 256, 256>>>(out, b3, total);
}

// round 10
// speedup vs baseline: 1.5808x; 1.1399x over previous
#include <cuda_runtime.h>
#include <cstdint>

// Problem constants (fixed shapes from the reference)
#define BB   2
#define NN   50000
#define FF   16
#define EE   1600000
#define EH   32      // hidden
#define EOUT 30      // second layer out (padded to 32 internally)
#define NOUT 16      // final out per node

__device__ __forceinline__ float sigmoidf_(float x) {
    return __fdividef(1.0f, 1.0f + __expf(-x));
}

__device__ __forceinline__ unsigned tf32_(float x) {
    unsigned r;
    asm("cvt.rna.tf32.f32 %0, %1;" : "=r"(r) : "f"(x));
    return r;
}

__device__ __forceinline__ void mma_tf32(float c[4], const unsigned a[4],
                                         unsigned b0, unsigned b1) {
    asm("mma.sync.aligned.m16n8k8.row.col.f32.tf32.tf32.f32 "
        "{%0,%1,%2,%3}, {%4,%5,%6,%7}, {%8,%9}, {%0,%1,%2,%3};"
        : "+f"(c[0]), "+f"(c[1]), "+f"(c[2]), "+f"(c[3])
        : "r"(a[0]), "r"(a[1]), "r"(a[2]), "r"(a[3]), "r"(b0), "r"(b1));
}

__device__ __forceinline__ void red_add2(float* p, float a, float b) {
    asm volatile("red.global.add.v2.f32 [%0], {%1,%2};"
                 :: "l"(p), "f"(a), "f"(b) : "memory");
}

// Per-node, per-batch layer-1 partials (scalar fp32), 128B rows:
// g_A[(b*NN+n)*32 + j] = x[b,n] @ W1[0:16, j] + b1[j]
// g_B[(b*NN+n)*32 + j] = x[b,n] @ W1[16:32, j]
__device__ __align__(128) float g_A[BB * NN * EH];   // 12.8 MB
__device__ __align__(128) float g_B[BB * NN * EH];   // 12.8 MB

__global__ void zero_kernel(float4* __restrict__ out, int n4) {
    int i = blockIdx.x * blockDim.x + threadIdx.x;
    if (i < n4) out[i] = make_float4(0.f, 0.f, 0.f, 0.f);
}

// One thread per (node, batch): builds A/B tables.
__global__ __launch_bounds__(128) void node_kernel(
    const float* __restrict__ nf,    // (B, N, F)
    const float* __restrict__ W1,    // (33, 32)
    const float* __restrict__ b1)    // (32)
{
    __shared__ __align__(16) float sW1[32 * 32];
    __shared__ __align__(16) float sb1[32];

    const int t = threadIdx.x;
    for (int i = t; i < 32 * 32; i += 128) sW1[i] = W1[i];
    if (t < 32) sb1[t] = b1[t];
    __syncthreads();

    const int idx = blockIdx.x * 128 + t;          // 0 .. BB*NN-1
    if (idx >= BB * NN) return;

    const float4* xv = (const float4*)(nf + (size_t)idx * FF);
    float x[16];
    #pragma unroll
    for (int q = 0; q < 4; q++) {
        float4 v = xv[q];
        x[4*q+0] = v.x; x[4*q+1] = v.y; x[4*q+2] = v.z; x[4*q+3] = v.w;
    }

    float accA[32], accB[32];
    #pragma unroll
    for (int j = 0; j < 32; j++) { accA[j] = sb1[j]; accB[j] = 0.0f; }
    #pragma unroll
    for (int k = 0; k < 16; k++) {
        const float xa = x[k];
        #pragma unroll
        for (int j = 0; j < 32; j++) {
            accA[j] = fmaf(xa, sW1[k * 32 + j], accA[j]);
            accB[j] = fmaf(xa, sW1[(16 + k) * 32 + j], accB[j]);
        }
    }
    float4* da = (float4*)(g_A + (size_t)idx * EH);
    float4* db = (float4*)(g_B + (size_t)idx * EH);
    #pragma unroll
    for (int q = 0; q < 8; q++) {
        da[q] = make_float4(accA[4*q+0], accA[4*q+1], accA[4*q+2], accA[4*q+3]);
        db[q] = make_float4(accB[4*q+0], accB[4*q+1], accB[4*q+2], accB[4*q+3]);
    }
}

// One thread per (edge, batch); warp-cooperative gather; tf32 mma for L2/L3.
// Block = 128 threads (4 warps). Each warp processes 32 edges independently.
#define SLOT_F 36    // gather staging slot stride (144 B)
#define MSTR  33     // matrix staging stride (conflict-free row stores)
__global__ __launch_bounds__(128) void edge_kernel(
    const float* __restrict__ ew,          // (B, E)
    const int*   __restrict__ eidx,        // (2, E) int32 (or int64 -- probed)
    const float* __restrict__ W1,          // (33, 32) -- only row 32 used here
    const float* __restrict__ W2,          // (32, 30)
    const float* __restrict__ b2,          // (30)
    const float* __restrict__ W3,          // (30, 16)
    float* __restrict__ out)               // (B, N, 16) accumulator
{
    __shared__ __align__(16) unsigned sW2tf[32 * MSTR];  // tf32 bits, cols 30..31 zero
    __shared__ __align__(16) unsigned sW3tf[32 * 17];    // tf32 bits, rows 30..31 zero
    __shared__ __align__(16) float sW1L[32];             // W1 row 32 (edge-weight row)
    __shared__ __align__(16) float sb2[32];              // padded zero
    __shared__ __align__(16) float stage[4][32 * SLOT_F];  // per-warp staging (>=32*MSTR)
    __shared__ int s_is64;

    const int t = threadIdx.x;
    for (int i = t; i < 32 * 32; i += 128) {
        int k = i >> 5, j = i & 31;
        sW2tf[k * MSTR + j] = tf32_((j < EOUT) ? W2[k * EOUT + j] : 0.0f);
    }
    for (int i = t; i < 32 * 16; i += 128) {
        int k = i >> 4, j = i & 15;
        sW3tf[k * 17 + j] = tf32_((k < EOUT) ? W3[k * 16 + j] : 0.0f);
    }
    if (t < 32) sW1L[t] = W1[32 * 32 + t];
    if (t < 32) sb2[t] = (t < EOUT) ? b2[t] : 0.0f;
    if (t == 0) {
        // int64 probe: little-endian int64 (<2^31) => odd int32 words are 0.
        s_is64 = (eidx[1] == 0 && eidx[3] == 0 && eidx[5] == 0 && eidx[7] == 0);
    }
    __syncthreads();

    const int wid  = t >> 5;
    const int lane = t & 31;
    const int g4   = lane >> 2;   // groupID (0..7)
    const int t4   = lane & 3;    // thread-in-group
    const int e = blockIdx.x * 128 + t;
    const int b = blockIdx.y;

    int src, tgt;
    if (s_is64) {
        src = eidx[2 * (size_t)e];
        tgt = eidx[2 * ((size_t)EE + e)];
    } else {
        src = eidx[e];
        tgt = eidx[EE + e];
    }

    const float w = __ldg(ew + (size_t)b * EE + e);

    // ---- preload B fragments (weights, shared across all edges) ----
    // k-tile k covers global k rows [8k, 8k+8): thread rows 8k+t4, 8k+t4+4.
    uint2 bw2[4][4];   // [k-tile][n-tile]
    #pragma unroll
    for (int k = 0; k < 4; k++)
        #pragma unroll
        for (int n = 0; n < 4; n++) {
            bw2[k][n].x = sW2tf[(8*k + t4) * MSTR + 8*n + g4];
            bw2[k][n].y = sW2tf[(8*k + t4 + 4) * MSTR + 8*n + g4];
        }
    uint2 bw3[4][2];
    #pragma unroll
    for (int k = 0; k < 4; k++)
        #pragma unroll
        for (int n = 0; n < 2; n++) {
            bw3[k][n].x = sW3tf[(8*k + t4) * 17 + 8*n + g4];
            bw3[k][n].y = sW3tf[(8*k + t4 + 4) * 17 + 8*n + g4];
        }

    float* buf = stage[wid];
    const int chunk = lane & 7;   // which 16B chunk of a row
    const int sub   = lane >> 3;  // which of 4 rows this round

    float h1[32];

    // ---- stage A rows (coalesced: 8 lanes cover one 128B row) ----
    {
        const float* baseA = g_A + (size_t)b * NN * EH;
        #pragma unroll
        for (int i = 0; i < 8; i++) {
            const int eo  = i * 4 + sub;
            const int row = __shfl_sync(0xffffffffu, src, eo);
            const float4 v = *(const float4*)(baseA + (size_t)row * EH + chunk * 4);
            *(float4*)(buf + eo * SLOT_F + chunk * 4) = v;
        }
        __syncwarp();
        const float4* r = (const float4*)(buf + lane * SLOT_F);
        #pragma unroll
        for (int q = 0; q < 8; q++) {
            float4 v = r[q];
            h1[4*q+0] = v.x; h1[4*q+1] = v.y; h1[4*q+2] = v.z; h1[4*q+3] = v.w;
        }
        __syncwarp();
    }
    // ---- stage B rows ----
    {
        const float* baseB = g_B + (size_t)b * NN * EH;
        #pragma unroll
        for (int i = 0; i < 8; i++) {
            const int eo  = i * 4 + sub;
            const int row = __shfl_sync(0xffffffffu, tgt, eo);
            const float4 v = *(const float4*)(baseB + (size_t)row * EH + chunk * 4);
            *(float4*)(buf + eo * SLOT_F + chunk * 4) = v;
        }
        __syncwarp();
        const float4* r = (const float4*)(buf + lane * SLOT_F);
        #pragma unroll
        for (int q = 0; q < 8; q++) {
            float4 v = r[q];
            h1[4*q+0] += v.x; h1[4*q+1] += v.y; h1[4*q+2] += v.z; h1[4*q+3] += v.w;
        }
        __syncwarp();
    }

    // ---- layer 1 activation: h1 = sigmoid(h1 + w * W1_last) ----
    #pragma unroll
    for (int j = 0; j < 32; j++)
        h1[j] = sigmoidf_(fmaf(w, sW1L[j], h1[j]));

    unsigned* bufu = (unsigned*)buf;

    // ---- transpose h1 into A-fragment layout via SMEM (row = edge-in-warp) ----
    #pragma unroll
    for (int j = 0; j < 32; j++)
        bufu[lane * MSTR + j] = tf32_(h1[j]);   // conflict-free: bank (lane+j)%32
    __syncwarp();

    unsigned a[2][4][4];   // [m-tile][k-tile][reg]; k-tile cols 8k+t4, 8k+t4+4
    #pragma unroll
    for (int m = 0; m < 2; m++)
        #pragma unroll
        for (int k = 0; k < 4; k++) {
            const int r0 = 16*m + g4;
            a[m][k][0] = bufu[r0 * MSTR + 8*k + t4];
            a[m][k][1] = bufu[(r0 + 8) * MSTR + 8*k + t4];
            a[m][k][2] = bufu[r0 * MSTR + 8*k + t4 + 4];
            a[m][k][3] = bufu[(r0 + 8) * MSTR + 8*k + t4 + 4];
        }

    // ---- layer 2 on tensor cores: c = h1 @ W2 + b2 ----
    float c[2][4][4];
    #pragma unroll
    for (int m = 0; m < 2; m++)
        #pragma unroll
        for (int n = 0; n < 4; n++) {
            float v0 = sb2[8*n + 2*t4];
            float v1 = sb2[8*n + 2*t4 + 1];
            c[m][n][0] = v0; c[m][n][1] = v1; c[m][n][2] = v0; c[m][n][3] = v1;
        }
    #pragma unroll
    for (int k = 0; k < 4; k++)
        #pragma unroll
        for (int m = 0; m < 2; m++)
            #pragma unroll
            for (int n = 0; n < 4; n++)
                mma_tf32(c[m][n], a[m][k], bw2[k][n].x, bw2[k][n].y);

    // ---- sigmoid + transpose C-layout -> A-fragment layout ----
    __syncwarp();
    #pragma unroll
    for (int m = 0; m < 2; m++)
        #pragma unroll
        for (int n = 0; n < 4; n++) {
            const int r0 = 16*m + g4;
            const int cc = 8*n + 2*t4;
            bufu[r0 * MSTR + cc]       = tf32_(sigmoidf_(c[m][n][0]));
            bufu[r0 * MSTR + cc + 1]   = tf32_(sigmoidf_(c[m][n][1]));
            bufu[(r0+8) * MSTR + cc]   = tf32_(sigmoidf_(c[m][n][2]));
            bufu[(r0+8) * MSTR + cc+1] = tf32_(sigmoidf_(c[m][n][3]));
        }
    __syncwarp();
    #pragma unroll
    for (int m = 0; m < 2; m++)
        #pragma unroll
        for (int k = 0; k < 4; k++) {
            const int r0 = 16*m + g4;
            a[m][k][0] = bufu[r0 * MSTR + 8*k + t4];
            a[m][k][1] = bufu[(r0 + 8) * MSTR + 8*k + t4];
            a[m][k][2] = bufu[r0 * MSTR + 8*k + t4 + 4];
            a[m][k][3] = bufu[(r0 + 8) * MSTR + 8*k + t4 + 4];
        }

    // ---- layer 3 on tensor cores: d = h2 @ W3 (b3 folded in finalize) ----
    float d[2][2][4];
    #pragma unroll
    for (int m = 0; m < 2; m++)
        #pragma unroll
        for (int n = 0; n < 2; n++)
            d[m][n][0] = d[m][n][1] = d[m][n][2] = d[m][n][3] = 0.0f;
    #pragma unroll
    for (int k = 0; k < 4; k++)
        #pragma unroll
        for (int m = 0; m < 2; m++)
            #pragma unroll
            for (int n = 0; n < 2; n++)
                mma_tf32(d[m][n], a[m][k], bw3[k][n].x, bw3[k][n].y);

    // ---- scatter directly from C layout: rows g4+8i, cols 2t4(+1), 8+2t4(+1) ----
    #pragma unroll
    for (int i = 0; i < 4; i++) {
        const int m  = i >> 1;
        const int hi = (i & 1) * 2;          // 0 -> c0/c1 (row r0), 2 -> c2/c3 (row r0+8)
        const int row = g4 + 8 * i;          // rows: g4, g4+8, g4+16, g4+24
        const int rsrc = __shfl_sync(0xffffffffu, src, row);
        const int rtgt = __shfl_sync(0xffffffffu, tgt, row);
        const float v0 = d[m][0][hi], v1 = d[m][0][hi + 1];
        const float v2 = d[m][1][hi], v3 = d[m][1][hi + 1];
        float* pt = out + ((size_t)b * NN + rtgt) * NOUT;
        float* ps = out + ((size_t)b * NN + rsrc) * NOUT;
        red_add2(pt + 2*t4,      v0,  v1);
        red_add2(pt + 8 + 2*t4,  v2,  v3);
        red_add2(ps + 2*t4,     -v0, -v1);
        red_add2(ps + 8 + 2*t4, -v2, -v3);
    }
}

__global__ void finalize_kernel(float* __restrict__ out,
                                const float* __restrict__ b3, int n) {
    int i = blockIdx.x * blockDim.x + threadIdx.x;
    if (i < n) {
        float v = out[i] + __ldg(b3 + (i & 15));
        out[i] = sigmoidf_(v);
    }
}

extern "C" void kernel_launch(void* const* d_in, const int* in_sizes, int n_in,
                              void* d_out, int out_size) {
    const float* nf   = (const float*)d_in[0];      // node_features (B,N,F)
    const float* ew   = (const float*)d_in[1];      // edge_weight   (B,E)
    const int*   eidx = (const int*)d_in[2];        // edge_index    (2,E)
    const float* W1   = (const float*)d_in[3];
    const float* b1   = (const float*)d_in[4];
    const float* W2   = (const float*)d_in[5];
    const float* b2   = (const float*)d_in[6];
    const float* W3   = (const float*)d_in[7];
    const float* b3   = (const float*)d_in[8];
    float* out = (float*)d_out;

    const int total = BB * NN * NOUT;  // 1,600,000 floats
    const int n4 = total / 4;

    zero_kernel<<<(n4 + 255) / 256, 256>>>((float4*)out, n4);
    node_kernel<<<(BB * NN + 127) / 128, 128>>>(nf, W1, b1);

    dim3 grid(EE / 128, BB);   // EE % 128 == 0 -> all warps full
    edge_kernel<<<grid, 128>>>(ew, eidx, W1, W2, b2, W3, out);

    finalize_kernel<<<(total + 255) / 256, 256>>>(out, b3, total);
}

// round 11
// speedup vs baseline: 1.7589x; 1.1127x over previous
#include <cuda_runtime.h>
#include <cstdint>

// Problem constants (fixed shapes from the reference)
#define BB   2
#define NN   50000
#define FF   16
#define EE   1600000
#define EH   32      // hidden
#define EOUT 30      // second layer out (padded to 32 internally)
#define NOUT 16      // final out per node

__device__ __forceinline__ float sigmoidf_(float x) {          // precise (finalize)
    return __fdividef(1.0f, 1.0f + __expf(-x));
}
__device__ __forceinline__ float sigmoid_fast(float x) {       // tanh-based (edge MLP)
    float t;
    asm("tanh.approx.f32 %0, %1;" : "=f"(t) : "f"(x * 0.5f));
    return fmaf(t, 0.5f, 0.5f);
}

__device__ __forceinline__ unsigned tf32_(float x) {
    unsigned r;
    asm("cvt.rna.tf32.f32 %0, %1;" : "=r"(r) : "f"(x));
    return r;
}

__device__ __forceinline__ void mma_tf32(float c[4], const unsigned a[4],
                                         unsigned b0, unsigned b1) {
    asm("mma.sync.aligned.m16n8k8.row.col.f32.tf32.tf32.f32 "
        "{%0,%1,%2,%3}, {%4,%5,%6,%7}, {%8,%9}, {%0,%1,%2,%3};"
        : "+f"(c[0]), "+f"(c[1]), "+f"(c[2]), "+f"(c[3])
        : "r"(a[0]), "r"(a[1]), "r"(a[2]), "r"(a[3]), "r"(b0), "r"(b1));
}

__device__ __forceinline__ void red_add2(float* p, float a, float b) {
    asm volatile("red.global.add.v2.f32 [%0], {%1,%2};"
                 :: "l"(p), "f"(a), "f"(b) : "memory");
}

// Per-node, per-batch layer-1 partials (scalar fp32), 128B rows:
// g_A[(b*NN+n)*32 + j] = x[b,n] @ W1[0:16, j] + b1[j]
// g_B[(b*NN+n)*32 + j] = x[b,n] @ W1[16:32, j]
__device__ __align__(128) float g_A[BB * NN * EH];   // 12.8 MB
__device__ __align__(128) float g_B[BB * NN * EH];   // 12.8 MB

__global__ void zero_kernel(float4* __restrict__ out, int n4) {
    int i = blockIdx.x * blockDim.x + threadIdx.x;
    if (i < n4) out[i] = make_float4(0.f, 0.f, 0.f, 0.f);
}

// One thread per (node, batch): builds A/B tables.
__global__ __launch_bounds__(128) void node_kernel(
    const float* __restrict__ nf,    // (B, N, F)
    const float* __restrict__ W1,    // (33, 32)
    const float* __restrict__ b1)    // (32)
{
    __shared__ __align__(16) float sW1[32 * 32];
    __shared__ __align__(16) float sb1[32];

    const int t = threadIdx.x;
    for (int i = t; i < 32 * 32; i += 128) sW1[i] = W1[i];
    if (t < 32) sb1[t] = b1[t];
    __syncthreads();

    const int idx = blockIdx.x * 128 + t;          // 0 .. BB*NN-1
    if (idx >= BB * NN) return;

    const float4* xv = (const float4*)(nf + (size_t)idx * FF);
    float x[16];
    #pragma unroll
    for (int q = 0; q < 4; q++) {
        float4 v = xv[q];
        x[4*q+0] = v.x; x[4*q+1] = v.y; x[4*q+2] = v.z; x[4*q+3] = v.w;
    }

    float accA[32], accB[32];
    #pragma unroll
    for (int j = 0; j < 32; j++) { accA[j] = sb1[j]; accB[j] = 0.0f; }
    #pragma unroll
    for (int k = 0; k < 16; k++) {
        const float xa = x[k];
        #pragma unroll
        for (int j = 0; j < 32; j++) {
            accA[j] = fmaf(xa, sW1[k * 32 + j], accA[j]);
            accB[j] = fmaf(xa, sW1[(16 + k) * 32 + j], accB[j]);
        }
    }
    float4* da = (float4*)(g_A + (size_t)idx * EH);
    float4* db = (float4*)(g_B + (size_t)idx * EH);
    #pragma unroll
    for (int q = 0; q < 8; q++) {
        da[q] = make_float4(accA[4*q+0], accA[4*q+1], accA[4*q+2], accA[4*q+3]);
        db[q] = make_float4(accB[4*q+0], accB[4*q+1], accB[4*q+2], accB[4*q+3]);
    }
}

// One thread per (edge, batch); warp-cooperative gather; tf32 mma for L2/L3.
// Block = 128 threads (4 warps). Each warp processes 32 edges independently.
// Weight fragments live in SMEM in fragment-order, loaded at use (low reg pressure).
#define SLOT_F 36    // gather staging slot stride (144 B)
#define MSTR  33     // matrix staging stride (conflict-free row stores)
__global__ __launch_bounds__(128) void edge_kernel(
    const float* __restrict__ ew,          // (B, E)
    const int*   __restrict__ eidx,        // (2, E) int32 (or int64 -- probed)
    const float* __restrict__ W1,          // (33, 32) -- only row 32 used here
    const float* __restrict__ W2,          // (32, 30)
    const float* __restrict__ b2,          // (30)
    const float* __restrict__ W3,          // (30, 16)
    float* __restrict__ out)               // (B, N, 16) accumulator
{
    __shared__ __align__(16) uint2 sW2f[4 * 4 * 4 * 8];  // [k][n][t4][g4], tf32 pair
    __shared__ __align__(16) uint2 sW3f[4 * 2 * 4 * 8];  // [k][n][t4][g4], tf32 pair
    __shared__ __align__(16) float sW1L[32];             // W1 row 32 (edge-weight row)
    __shared__ __align__(16) float sb2[32];              // padded zero
    __shared__ __align__(16) float stage[4][32 * SLOT_F];  // per-warp staging (>=32*MSTR)
    __shared__ int s_is64;

    const int t = threadIdx.x;
    // W2 fragments: k-tile k rows {8k+t4, 8k+t4+4}, col 8n+g4 (cols >= 30 zero)
    for (int i = t; i < 512; i += 128) {
        const int g = i & 7, t4i = (i >> 3) & 3, n = (i >> 5) & 3, k = i >> 7;
        const int col = 8 * n + g;
        const int r0 = 8 * k + t4i, r1 = r0 + 4;
        const float v0 = (col < EOUT) ? W2[r0 * EOUT + col] : 0.0f;
        const float v1 = (col < EOUT) ? W2[r1 * EOUT + col] : 0.0f;
        sW2f[i] = make_uint2(tf32_(v0), tf32_(v1));
    }
    // W3 fragments: rows >= 30 zero (k-dim pad)
    for (int i = t; i < 256; i += 128) {
        const int g = i & 7, t4i = (i >> 3) & 3, n = (i >> 5) & 1, k = i >> 6;
        const int col = 8 * n + g;
        const int r0 = 8 * k + t4i, r1 = r0 + 4;
        const float v0 = (r0 < EOUT) ? W3[r0 * 16 + col] : 0.0f;
        const float v1 = (r1 < EOUT) ? W3[r1 * 16 + col] : 0.0f;
        sW3f[i] = make_uint2(tf32_(v0), tf32_(v1));
    }
    if (t < 32) sW1L[t] = W1[32 * 32 + t];
    if (t < 32) sb2[t] = (t < EOUT) ? b2[t] : 0.0f;
    if (t == 0) {
        // int64 probe: little-endian int64 (<2^31) => odd int32 words are 0.
        s_is64 = (eidx[1] == 0 && eidx[3] == 0 && eidx[5] == 0 && eidx[7] == 0);
    }
    __syncthreads();

    const int wid  = t >> 5;
    const int lane = t & 31;
    const int g4   = lane >> 2;   // groupID (0..7)
    const int t4   = lane & 3;    // thread-in-group
    const int e = blockIdx.x * 128 + t;
    const int b = blockIdx.y;

    int src, tgt;
    if (s_is64) {
        src = eidx[2 * (size_t)e];
        tgt = eidx[2 * ((size_t)EE + e)];
    } else {
        src = eidx[e];
        tgt = eidx[EE + e];
    }

    const float w = __ldg(ew + (size_t)b * EE + e);

    float* buf = stage[wid];
    const int chunk = lane & 7;   // which 16B chunk of a row
    const int sub   = lane >> 3;  // which of 4 rows this round

    float h1[32];

    // ---- stage A rows (coalesced: 8 lanes cover one 128B row) ----
    {
        const float* baseA = g_A + (size_t)b * NN * EH;
        #pragma unroll
        for (int i = 0; i < 8; i++) {
            const int eo  = i * 4 + sub;
            const int row = __shfl_sync(0xffffffffu, src, eo);
            const float4 v = *(const float4*)(baseA + (size_t)row * EH + chunk * 4);
            *(float4*)(buf + eo * SLOT_F + chunk * 4) = v;
        }
        __syncwarp();
        const float4* r = (const float4*)(buf + lane * SLOT_F);
        #pragma unroll
        for (int q = 0; q < 8; q++) {
            float4 v = r[q];
            h1[4*q+0] = v.x; h1[4*q+1] = v.y; h1[4*q+2] = v.z; h1[4*q+3] = v.w;
        }
        __syncwarp();
    }
    // ---- stage B rows ----
    {
        const float* baseB = g_B + (size_t)b * NN * EH;
        #pragma unroll
        for (int i = 0; i < 8; i++) {
            const int eo  = i * 4 + sub;
            const int row = __shfl_sync(0xffffffffu, tgt, eo);
            const float4 v = *(const float4*)(baseB + (size_t)row * EH + chunk * 4);
            *(float4*)(buf + eo * SLOT_F + chunk * 4) = v;
        }
        __syncwarp();
        const float4* r = (const float4*)(buf + lane * SLOT_F);
        #pragma unroll
        for (int q = 0; q < 8; q++) {
            float4 v = r[q];
            h1[4*q+0] += v.x; h1[4*q+1] += v.y; h1[4*q+2] += v.z; h1[4*q+3] += v.w;
        }
        __syncwarp();
    }

    // ---- layer 1 activation: h1 = sigmoid(h1 + w * W1_last) ----
    #pragma unroll
    for (int j = 0; j < 32; j++)
        h1[j] = sigmoid_fast(fmaf(w, sW1L[j], h1[j]));

    unsigned* bufu = (unsigned*)buf;

    // ---- transpose h1 into A-fragment layout via SMEM (row = edge-in-warp) ----
    #pragma unroll
    for (int j = 0; j < 32; j++)
        bufu[lane * MSTR + j] = tf32_(h1[j]);   // conflict-free: bank (lane+j)%32
    __syncwarp();

    unsigned a[2][4][4];   // [m-tile][k-tile][reg]; k-tile cols 8k+t4, 8k+t4+4
    #pragma unroll
    for (int m = 0; m < 2; m++)
        #pragma unroll
        for (int k = 0; k < 4; k++) {
            const int r0 = 16*m + g4;
            a[m][k][0] = bufu[r0 * MSTR + 8*k + t4];
            a[m][k][1] = bufu[(r0 + 8) * MSTR + 8*k + t4];
            a[m][k][2] = bufu[r0 * MSTR + 8*k + t4 + 4];
            a[m][k][3] = bufu[(r0 + 8) * MSTR + 8*k + t4 + 4];
        }

    // ---- layer 2 on tensor cores: c = h1 @ W2 + b2 ----
    float c[2][4][4];
    #pragma unroll
    for (int m = 0; m < 2; m++)
        #pragma unroll
        for (int n = 0; n < 4; n++) {
            float v0 = sb2[8*n + 2*t4];
            float v1 = sb2[8*n + 2*t4 + 1];
            c[m][n][0] = v0; c[m][n][1] = v1; c[m][n][2] = v0; c[m][n][3] = v1;
        }
    #pragma unroll
    for (int k = 0; k < 4; k++)
        #pragma unroll
        for (int n = 0; n < 4; n++) {
            const uint2 bw = sW2f[((k * 4 + n) * 4 + t4) * 8 + g4];
            #pragma unroll
            for (int m = 0; m < 2; m++)
                mma_tf32(c[m][n], a[m][k], bw.x, bw.y);
        }

    // ---- sigmoid + transpose C-layout -> A-fragment layout ----
    __syncwarp();
    #pragma unroll
    for (int m = 0; m < 2; m++)
        #pragma unroll
        for (int n = 0; n < 4; n++) {
            const int r0 = 16*m + g4;
            const int cc = 8*n + 2*t4;
            bufu[r0 * MSTR + cc]       = tf32_(sigmoid_fast(c[m][n][0]));
            bufu[r0 * MSTR + cc + 1]   = tf32_(sigmoid_fast(c[m][n][1]));
            bufu[(r0+8) * MSTR + cc]   = tf32_(sigmoid_fast(c[m][n][2]));
            bufu[(r0+8) * MSTR + cc+1] = tf32_(sigmoid_fast(c[m][n][3]));
        }
    __syncwarp();
    #pragma unroll
    for (int m = 0; m < 2; m++)
        #pragma unroll
        for (int k = 0; k < 4; k++) {
            const int r0 = 16*m + g4;
            a[m][k][0] = bufu[r0 * MSTR + 8*k + t4];
            a[m][k][1] = bufu[(r0 + 8) * MSTR + 8*k + t4];
            a[m][k][2] = bufu[r0 * MSTR + 8*k + t4 + 4];
            a[m][k][3] = bufu[(r0 + 8) * MSTR + 8*k + t4 + 4];
        }

    // ---- layer 3 on tensor cores: d = h2 @ W3 (b3 folded in finalize) ----
    float d[2][2][4];
    #pragma unroll
    for (int m = 0; m < 2; m++)
        #pragma unroll
        for (int n = 0; n < 2; n++)
            d[m][n][0] = d[m][n][1] = d[m][n][2] = d[m][n][3] = 0.0f;
    #pragma unroll
    for (int k = 0; k < 4; k++)
        #pragma unroll
        for (int n = 0; n < 2; n++) {
            const uint2 bw = sW3f[((k * 2 + n) * 4 + t4) * 8 + g4];
            #pragma unroll
            for (int m = 0; m < 2; m++)
                mma_tf32(d[m][n], a[m][k], bw.x, bw.y);
        }

    // ---- scatter directly from C layout: rows g4+8i, cols 2t4(+1), 8+2t4(+1) ----
    #pragma unroll
    for (int i = 0; i < 4; i++) {
        const int m  = i >> 1;
        const int hi = (i & 1) * 2;          // 0 -> c0/c1 (row r0), 2 -> c2/c3 (row r0+8)
        const int row = g4 + 8 * i;          // rows: g4, g4+8, g4+16, g4+24
        const int rsrc = __shfl_sync(0xffffffffu, src, row);
        const int rtgt = __shfl_sync(0xffffffffu, tgt, row);
        const float v0 = d[m][0][hi], v1 = d[m][0][hi + 1];
        const float v2 = d[m][1][hi], v3 = d[m][1][hi + 1];
        float* pt = out + ((size_t)b * NN + rtgt) * NOUT;
        float* ps = out + ((size_t)b * NN + rsrc) * NOUT;
        red_add2(pt + 2*t4,      v0,  v1);
        red_add2(pt + 8 + 2*t4,  v2,  v3);
        red_add2(ps + 2*t4,     -v0, -v1);
        red_add2(ps + 8 + 2*t4, -v2, -v3);
    }
}

__global__ void finalize_kernel(float* __restrict__ out,
                                const float* __restrict__ b3, int n) {
    int i = blockIdx.x * blockDim.x + threadIdx.x;
    if (i < n) {
        float v = out[i] + __ldg(b3 + (i & 15));
        out[i] = sigmoidf_(v);
    }
}

extern "C" void kernel_launch(void* const* d_in, const int* in_sizes, int n_in,
                              void* d_out, int out_size) {
    const float* nf   = (const float*)d_in[0];      // node_features (B,N,F)
    const float* ew   = (const float*)d_in[1];      // edge_weight   (B,E)
    const int*   eidx = (const int*)d_in[2];        // edge_index    (2,E)
    const float* W1   = (const float*)d_in[3];
    const float* b1   = (const float*)d_in[4];
    const float* W2   = (const float*)d_in[5];
    const float* b2   = (const float*)d_in[6];
    const float* W3   = (const float*)d_in[7];
    const float* b3   = (const float*)d_in[8];
    float* out = (float*)d_out;

    const int total = BB * NN * NOUT;  // 1,600,000 floats
    const int n4 = total / 4;

    zero_kernel<<<(n4 + 255) / 256, 256>>>((float4*)out, n4);
    node_kernel<<<(BB * NN + 127) / 128, 128>>>(nf, W1, b1);

    dim3 grid(EE / 128, BB);   // EE % 128 == 0 -> all warps full
    edge_kernel<<<grid, 128>>>(ew, eidx, W1, W2, b2, W3, out);

    finalize_kernel<<<(total + 255) / 256, 256>>>(out, b3, total);
}

// round 12
// speedup vs baseline: 2.1665x; 1.2318x over previous
#include <cuda_runtime.h>
#include <cstdint>

// Problem constants (fixed shapes from the reference)
#define BB   2
#define NN   50000
#define FF   16
#define EE   1600000
#define EH   32      // hidden
#define EOUT 30      // second layer out (padded to 32 internally)
#define NOUT 16      // final out per node

__device__ __forceinline__ float sigmoidf_(float x) {          // precise (finalize)
    return __fdividef(1.0f, 1.0f + __expf(-x));
}
__device__ __forceinline__ float sigmoid_fast(float x) {       // tanh-based (edge MLP)
    float t;
    asm("tanh.approx.f32 %0, %1;" : "=f"(t) : "f"(x * 0.5f));
    return fmaf(t, 0.5f, 0.5f);
}

__device__ __forceinline__ unsigned tf32_(float x) {
    unsigned r;
    asm("cvt.rna.tf32.f32 %0, %1;" : "=r"(r) : "f"(x));
    return r;
}

__device__ __forceinline__ void mma_tf32(float c[4], const unsigned a[4],
                                         unsigned b0, unsigned b1) {
    asm("mma.sync.aligned.m16n8k8.row.col.f32.tf32.tf32.f32 "
        "{%0,%1,%2,%3}, {%4,%5,%6,%7}, {%8,%9}, {%0,%1,%2,%3};"
        : "+f"(c[0]), "+f"(c[1]), "+f"(c[2]), "+f"(c[3])
        : "r"(a[0]), "r"(a[1]), "r"(a[2]), "r"(a[3]), "r"(b0), "r"(b1));
}

__device__ __forceinline__ void red_add2(float* p, float a, float b) {
    asm volatile("red.global.add.v2.f32 [%0], {%1,%2};"
                 :: "l"(p), "f"(a), "f"(b) : "memory");
}

// Per-node, per-batch layer-1 partials (scalar fp32), 128B rows:
// g_A[(b*NN+n)*32 + j] = x[b,n] @ W1[0:16, j] + b1[j]
// g_B[(b*NN+n)*32 + j] = x[b,n] @ W1[16:32, j]
__device__ __align__(128) float g_A[BB * NN * EH];   // 12.8 MB
__device__ __align__(128) float g_B[BB * NN * EH];   // 12.8 MB

__global__ void zero_kernel(float4* __restrict__ out, int n4) {
    int i = blockIdx.x * blockDim.x + threadIdx.x;
    if (i < n4) out[i] = make_float4(0.f, 0.f, 0.f, 0.f);
}

// One thread per (node, batch): builds A/B tables.
__global__ __launch_bounds__(128) void node_kernel(
    const float* __restrict__ nf,    // (B, N, F)
    const float* __restrict__ W1,    // (33, 32)
    const float* __restrict__ b1)    // (32)
{
    __shared__ __align__(16) float sW1[32 * 32];
    __shared__ __align__(16) float sb1[32];

    const int t = threadIdx.x;
    for (int i = t; i < 32 * 32; i += 128) sW1[i] = W1[i];
    if (t < 32) sb1[t] = b1[t];
    __syncthreads();

    const int idx = blockIdx.x * 128 + t;          // 0 .. BB*NN-1
    if (idx >= BB * NN) return;

    const float4* xv = (const float4*)(nf + (size_t)idx * FF);
    float x[16];
    #pragma unroll
    for (int q = 0; q < 4; q++) {
        float4 v = xv[q];
        x[4*q+0] = v.x; x[4*q+1] = v.y; x[4*q+2] = v.z; x[4*q+3] = v.w;
    }

    float accA[32], accB[32];
    #pragma unroll
    for (int j = 0; j < 32; j++) { accA[j] = sb1[j]; accB[j] = 0.0f; }
    #pragma unroll
    for (int k = 0; k < 16; k++) {
        const float xa = x[k];
        #pragma unroll
        for (int j = 0; j < 32; j++) {
            accA[j] = fmaf(xa, sW1[k * 32 + j], accA[j]);
            accB[j] = fmaf(xa, sW1[(16 + k) * 32 + j], accB[j]);
        }
    }
    float4* da = (float4*)(g_A + (size_t)idx * EH);
    float4* db = (float4*)(g_B + (size_t)idx * EH);
    #pragma unroll
    for (int q = 0; q < 8; q++) {
        da[q] = make_float4(accA[4*q+0], accA[4*q+1], accA[4*q+2], accA[4*q+3]);
        db[q] = make_float4(accB[4*q+0], accB[4*q+1], accB[4*q+2], accB[4*q+3]);
    }
}

// One thread per (edge, batch); warp-cooperative gather with fused layer-1;
// tf32 mma for L2/L3. Block = 128 threads (4 warps), 32 edges per warp.
#define SLOT_F 36    // gather staging slot stride (144 B)
#define MSTR  33     // matrix staging stride (conflict-free row stores)
__global__ __launch_bounds__(128) void edge_kernel(
    const float* __restrict__ ew,          // (B, E)
    const int*   __restrict__ eidx,        // (2, E) int32 (or int64 -- probed)
    const float* __restrict__ W1,          // (33, 32) -- only row 32 used here
    const float* __restrict__ W2,          // (32, 30)
    const float* __restrict__ b2,          // (30)
    const float* __restrict__ W3,          // (30, 16)
    float* __restrict__ out,               // (B, N, 16) accumulator
    int e0)                                // edge offset of this launch
{
    __shared__ __align__(16) uint2 sW2f[4 * 4 * 4 * 8];  // [k][n][t4][g4], tf32 pair
    __shared__ __align__(16) uint2 sW3f[4 * 2 * 4 * 8];  // [k][n][t4][g4], tf32 pair
    __shared__ __align__(16) float sW1L[32];             // W1 row 32 (edge-weight row)
    __shared__ __align__(16) float sb2[32];              // padded zero
    __shared__ __align__(16) float stage[4][32 * SLOT_F];  // per-warp staging (>=32*MSTR)
    __shared__ int s_is64;

    const int t = threadIdx.x;
    // W2 fragments: k-tile k rows {8k+t4, 8k+t4+4}, col 8n+g4 (cols >= 30 zero)
    for (int i = t; i < 512; i += 128) {
        const int g = i & 7, t4i = (i >> 3) & 3, n = (i >> 5) & 3, k = i >> 7;
        const int col = 8 * n + g;
        const int r0 = 8 * k + t4i, r1 = r0 + 4;
        const float v0 = (col < EOUT) ? W2[r0 * EOUT + col] : 0.0f;
        const float v1 = (col < EOUT) ? W2[r1 * EOUT + col] : 0.0f;
        sW2f[i] = make_uint2(tf32_(v0), tf32_(v1));
    }
    // W3 fragments: rows >= 30 zero (k-dim pad)
    for (int i = t; i < 256; i += 128) {
        const int g = i & 7, t4i = (i >> 3) & 3, n = (i >> 5) & 1, k = i >> 6;
        const int col = 8 * n + g;
        const int r0 = 8 * k + t4i, r1 = r0 + 4;
        const float v0 = (r0 < EOUT) ? W3[r0 * 16 + col] : 0.0f;
        const float v1 = (r1 < EOUT) ? W3[r1 * 16 + col] : 0.0f;
        sW3f[i] = make_uint2(tf32_(v0), tf32_(v1));
    }
    if (t < 32) sW1L[t] = W1[32 * 32 + t];
    if (t < 32) sb2[t] = (t < EOUT) ? b2[t] : 0.0f;
    if (t == 0) {
        // int64 probe: little-endian int64 (<2^31) => odd int32 words are 0.
        s_is64 = (eidx[1] == 0 && eidx[3] == 0 && eidx[5] == 0 && eidx[7] == 0);
    }
    __syncthreads();

    const int wid  = t >> 5;
    const int lane = t & 31;
    const int g4   = lane >> 2;   // groupID (0..7)
    const int t4   = lane & 3;    // thread-in-group
    const int e = e0 + blockIdx.x * 128 + t;
    const int b = blockIdx.y;

    int src, tgt;
    if (s_is64) {
        src = eidx[2 * (size_t)e];
        tgt = eidx[2 * ((size_t)EE + e)];
    } else {
        src = eidx[e];
        tgt = eidx[EE + e];
    }

    const float w = __ldg(ew + (size_t)b * EE + e);

    float* buf = stage[wid];
    const int chunk = lane & 7;   // which 16B chunk of a row
    const int sub   = lane >> 3;  // which of 4 rows this round

    // ---- stage A[src]+B[tgt] rows (coalesced; 8 lanes cover one 128B row) ----
    {
        const float* baseA = g_A + (size_t)b * NN * EH;
        const float* baseB = g_B + (size_t)b * NN * EH;
        #pragma unroll
        for (int i = 0; i < 8; i++) {
            const int eo = i * 4 + sub;                       // edge-in-warp
            const int rA = __shfl_sync(0xffffffffu, src, eo);
            const int rB = __shfl_sync(0xffffffffu, tgt, eo);
            float4 va = *(const float4*)(baseA + (size_t)rA * EH + chunk * 4);
            float4 vb = *(const float4*)(baseB + (size_t)rB * EH + chunk * 4);
            va.x += vb.x; va.y += vb.y; va.z += vb.z; va.w += vb.w;
            *(float4*)(buf + eo * SLOT_F + chunk * 4) = va;
        }
        __syncwarp();
    }

    // ---- fused layer 1 + A-fragment build ----
    // a[m][k][r]: value at (row = 16m+g4 (+8 for r=1,3), col = 8k+t4 (+4 for r=2,3))
    // h1 = sigmoid(staged + w_row * W1L[col]); w_row via shfl, W1L via LDS.
    float wr[4];
    #pragma unroll
    for (int i = 0; i < 4; i++) wr[i] = __shfl_sync(0xffffffffu, w, g4 + 8 * i);
    // rows g4, g4+8, g4+16, g4+24 -> wr[0..3]; row 16m+g4 -> wr[2m], +8 -> wr[2m+1]
    float wl[8];
    #pragma unroll
    for (int k = 0; k < 4; k++) {
        wl[2*k]   = sW1L[8*k + t4];
        wl[2*k+1] = sW1L[8*k + t4 + 4];
    }

    unsigned a[2][4][4];
    #pragma unroll
    for (int m = 0; m < 2; m++)
        #pragma unroll
        for (int k = 0; k < 4; k++) {
            const int rlo = (16*m + g4) * SLOT_F;
            const int rhi = (16*m + g4 + 8) * SLOT_F;
            a[m][k][0] = tf32_(sigmoid_fast(fmaf(wr[2*m],   wl[2*k],   buf[rlo + 8*k + t4])));
            a[m][k][1] = tf32_(sigmoid_fast(fmaf(wr[2*m+1], wl[2*k],   buf[rhi + 8*k + t4])));
            a[m][k][2] = tf32_(sigmoid_fast(fmaf(wr[2*m],   wl[2*k+1], buf[rlo + 8*k + t4 + 4])));
            a[m][k][3] = tf32_(sigmoid_fast(fmaf(wr[2*m+1], wl[2*k+1], buf[rhi + 8*k + t4 + 4])));
        }

    // ---- layer 2 on tensor cores: c = h1 @ W2 + b2 ----
    float c[2][4][4];
    #pragma unroll
    for (int m = 0; m < 2; m++)
        #pragma unroll
        for (int n = 0; n < 4; n++) {
            float v0 = sb2[8*n + 2*t4];
            float v1 = sb2[8*n + 2*t4 + 1];
            c[m][n][0] = v0; c[m][n][1] = v1; c[m][n][2] = v0; c[m][n][3] = v1;
        }
    #pragma unroll
    for (int k = 0; k < 4; k++)
        #pragma unroll
        for (int n = 0; n < 4; n++) {
            const uint2 bw = sW2f[((k * 4 + n) * 4 + t4) * 8 + g4];
            #pragma unroll
            for (int m = 0; m < 2; m++)
                mma_tf32(c[m][n], a[m][k], bw.x, bw.y);
        }

    // ---- sigmoid + transpose C-layout -> A-fragment layout (via staging buf) ----
    __syncwarp();   // all staged-value reads done before overwrite
    unsigned* bufu = (unsigned*)buf;
    #pragma unroll
    for (int m = 0; m < 2; m++)
        #pragma unroll
        for (int n = 0; n < 4; n++) {
            const int r0 = 16*m + g4;
            const int cc = 8*n + 2*t4;
            bufu[r0 * MSTR + cc]       = tf32_(sigmoid_fast(c[m][n][0]));
            bufu[r0 * MSTR + cc + 1]   = tf32_(sigmoid_fast(c[m][n][1]));
            bufu[(r0+8) * MSTR + cc]   = tf32_(sigmoid_fast(c[m][n][2]));
            bufu[(r0+8) * MSTR + cc+1] = tf32_(sigmoid_fast(c[m][n][3]));
        }
    __syncwarp();
    #pragma unroll
    for (int m = 0; m < 2; m++)
        #pragma unroll
        for (int k = 0; k < 4; k++) {
            const int r0 = 16*m + g4;
            a[m][k][0] = bufu[r0 * MSTR + 8*k + t4];
            a[m][k][1] = bufu[(r0 + 8) * MSTR + 8*k + t4];
            a[m][k][2] = bufu[r0 * MSTR + 8*k + t4 + 4];
            a[m][k][3] = bufu[(r0 + 8) * MSTR + 8*k + t4 + 4];
        }

    // ---- layer 3 on tensor cores: d = h2 @ W3 (b3 folded in finalize) ----
    float d[2][2][4];
    #pragma unroll
    for (int m = 0; m < 2; m++)
        #pragma unroll
        for (int n = 0; n < 2; n++)
            d[m][n][0] = d[m][n][1] = d[m][n][2] = d[m][n][3] = 0.0f;
    #pragma unroll
    for (int k = 0; k < 4; k++)
        #pragma unroll
        for (int n = 0; n < 2; n++) {
            const uint2 bw = sW3f[((k * 2 + n) * 4 + t4) * 8 + g4];
            #pragma unroll
            for (int m = 0; m < 2; m++)
                mma_tf32(d[m][n], a[m][k], bw.x, bw.y);
        }

    // ---- scatter directly from C layout: rows g4+8i, cols 2t4(+1), 8+2t4(+1) ----
    #pragma unroll
    for (int i = 0; i < 4; i++) {
        const int m  = i >> 1;
        const int hi = (i & 1) * 2;          // 0 -> c0/c1 (row r0), 2 -> c2/c3 (row r0+8)
        const int row = g4 + 8 * i;          // rows: g4, g4+8, g4+16, g4+24
        const int rsrc = __shfl_sync(0xffffffffu, src, row);
        const int rtgt = __shfl_sync(0xffffffffu, tgt, row);
        const float v0 = d[m][0][hi], v1 = d[m][0][hi + 1];
        const float v2 = d[m][1][hi], v3 = d[m][1][hi + 1];
        float* pt = out + ((size_t)b * NN + rtgt) * NOUT;
        float* ps = out + ((size_t)b * NN + rsrc) * NOUT;
        red_add2(pt + 2*t4,      v0,  v1);
        red_add2(pt + 8 + 2*t4,  v2,  v3);
        red_add2(ps + 2*t4,     -v0, -v1);
        red_add2(ps + 8 + 2*t4, -v2, -v3);
    }
}

__global__ void finalize_kernel(float* __restrict__ out,
                                const float* __restrict__ b3, int n) {
    int i = blockIdx.x * blockDim.x + threadIdx.x;
    if (i < n) {
        float v = out[i] + __ldg(b3 + (i & 15));
        out[i] = sigmoidf_(v);
    }
}

extern "C" void kernel_launch(void* const* d_in, const int* in_sizes, int n_in,
                              void* d_out, int out_size) {
    const float* nf   = (const float*)d_in[0];      // node_features (B,N,F)
    const float* ew   = (const float*)d_in[1];      // edge_weight   (B,E)
    const int*   eidx = (const int*)d_in[2];        // edge_index    (2,E)
    const float* W1   = (const float*)d_in[3];
    const float* b1   = (const float*)d_in[4];
    const float* W2   = (const float*)d_in[5];
    const float* b2   = (const float*)d_in[6];
    const float* W3   = (const float*)d_in[7];
    const float* b3   = (const float*)d_in[8];
    float* out = (float*)d_out;

    const int total = BB * NN * NOUT;  // 1,600,000 floats
    const int n4 = total / 4;

    zero_kernel<<<(n4 + 255) / 256, 256>>>((float4*)out, n4);
    node_kernel<<<(BB * NN + 127) / 128, 128>>>(nf, W1, b1);

    // Edge work split in two launches (also aligns ncu's -s 5 onto edge_kernel).
    dim3 grid((EE / 2) / 128, BB);   // EE % 256 == 0 -> all warps full
    edge_kernel<<<grid, 128>>>(ew, eidx, W1, W2, b2, W3, out, 0);
    edge_kernel<<<grid, 128>>>(ew, eidx, W1, W2, b2, W3, out, EE / 2);

    finalize_kernel<<<(total + 255) / 256, 256>>>(out, b3, total);
}

// round 13
// speedup vs baseline: 2.9570x; 1.3649x over previous
#include <cuda_runtime.h>
#include <cstdint>

// Problem constants (fixed shapes from the reference)
#define BB   2
#define NN   50000
#define FF   16
#define EE   1600000
#define EH   32      // hidden
#define EOUT 30      // second layer out (padded to 32 internally)
#define NOUT 16      // final out per node

__device__ __forceinline__ float sigmoidf_(float x) {          // precise (finalize)
    return __fdividef(1.0f, 1.0f + __expf(-x));
}
__device__ __forceinline__ float sigmoid_fast(float x) {       // tanh-based (edge MLP)
    float t;
    asm("tanh.approx.f32 %0, %1;" : "=f"(t) : "f"(x * 0.5f));
    return fmaf(t, 0.5f, 0.5f);
}

__device__ __forceinline__ unsigned tf32_(float x) {
    unsigned r;
    asm("cvt.rna.tf32.f32 %0, %1;" : "=r"(r) : "f"(x));
    return r;
}

__device__ __forceinline__ void mma_tf32(float c[4], const unsigned a[4],
                                         unsigned b0, unsigned b1) {
    asm("mma.sync.aligned.m16n8k8.row.col.f32.tf32.tf32.f32 "
        "{%0,%1,%2,%3}, {%4,%5,%6,%7}, {%8,%9}, {%0,%1,%2,%3};"
        : "+f"(c[0]), "+f"(c[1]), "+f"(c[2]), "+f"(c[3])
        : "r"(a[0]), "r"(a[1]), "r"(a[2]), "r"(a[3]), "r"(b0), "r"(b1));
}

__device__ __forceinline__ void red_add4(float* p, float a, float b, float c, float d) {
    asm volatile("red.global.add.v4.f32 [%0], {%1,%2,%3,%4};"
                 :: "l"(p), "f"(a), "f"(b), "f"(c), "f"(d) : "memory");
}

// Per-node, per-batch layer-1 partials (scalar fp32), 128B rows:
// g_A[(b*NN+n)*32 + j] = x[b,n] @ W1[0:16, j] + b1[j]
// g_B[(b*NN+n)*32 + j] = x[b,n] @ W1[16:32, j]
__device__ __align__(128) float g_A[BB * NN * EH];   // 12.8 MB
__device__ __align__(128) float g_B[BB * NN * EH];   // 12.8 MB

__global__ void zero_kernel(float4* __restrict__ out, int n4) {
    int i = blockIdx.x * blockDim.x + threadIdx.x;
    if (i < n4) out[i] = make_float4(0.f, 0.f, 0.f, 0.f);
}

// One thread per (node, batch): builds A/B tables.
__global__ __launch_bounds__(128) void node_kernel(
    const float* __restrict__ nf,    // (B, N, F)
    const float* __restrict__ W1,    // (33, 32)
    const float* __restrict__ b1)    // (32)
{
    __shared__ __align__(16) float sW1[32 * 32];
    __shared__ __align__(16) float sb1[32];

    const int t = threadIdx.x;
    for (int i = t; i < 32 * 32; i += 128) sW1[i] = W1[i];
    if (t < 32) sb1[t] = b1[t];
    __syncthreads();

    const int idx = blockIdx.x * 128 + t;          // 0 .. BB*NN-1
    if (idx >= BB * NN) return;

    const float4* xv = (const float4*)(nf + (size_t)idx * FF);
    float x[16];
    #pragma unroll
    for (int q = 0; q < 4; q++) {
        float4 v = xv[q];
        x[4*q+0] = v.x; x[4*q+1] = v.y; x[4*q+2] = v.z; x[4*q+3] = v.w;
    }

    float accA[32], accB[32];
    #pragma unroll
    for (int j = 0; j < 32; j++) { accA[j] = sb1[j]; accB[j] = 0.0f; }
    #pragma unroll
    for (int k = 0; k < 16; k++) {
        const float xa = x[k];
        #pragma unroll
        for (int j = 0; j < 32; j++) {
            accA[j] = fmaf(xa, sW1[k * 32 + j], accA[j]);
            accB[j] = fmaf(xa, sW1[(16 + k) * 32 + j], accB[j]);
        }
    }
    float4* da = (float4*)(g_A + (size_t)idx * EH);
    float4* db = (float4*)(g_B + (size_t)idx * EH);
    #pragma unroll
    for (int q = 0; q < 8; q++) {
        da[q] = make_float4(accA[4*q+0], accA[4*q+1], accA[4*q+2], accA[4*q+3]);
        db[q] = make_float4(accB[4*q+0], accB[4*q+1], accB[4*q+2], accB[4*q+3]);
    }
}

// One thread per (edge, batch); warp-cooperative gather with fused layer-1;
// tf32 mma for L2/L3. Block = 128 threads (4 warps), 32 edges per warp.
#define SLOT_F 36    // staging slot stride in floats (144 B); 36 % 32 == 4
__global__ __launch_bounds__(128) void edge_kernel(
    const float* __restrict__ ew,          // (B, E)
    const int*   __restrict__ eidx,        // (2, E) int32 (or int64 -- probed)
    const float* __restrict__ W1,          // (33, 32) -- only row 32 used here
    const float* __restrict__ W2,          // (32, 30)
    const float* __restrict__ b2,          // (30)
    const float* __restrict__ W3,          // (30, 16)
    float* __restrict__ out,               // (B, N, 16) accumulator
    int e0)                                // edge offset of this launch
{
    // Weight fragments, scalar-split (bank = lane -> conflict-free LDS.32):
    __shared__ __align__(16) unsigned sW2x[16 * 32];  // [(k*4+n)][lane] reg b0
    __shared__ __align__(16) unsigned sW2y[16 * 32];  // [(k*4+n)][lane] reg b1
    __shared__ __align__(16) unsigned sW3x[8 * 32];   // [(k*2+n)][lane]
    __shared__ __align__(16) unsigned sW3y[8 * 32];
    __shared__ __align__(16) float sW1L[32];          // W1 row 32 (edge-weight row)
    __shared__ __align__(16) float sb2[32];           // padded zero
    __shared__ __align__(16) float stage[4][32 * SLOT_F];  // per-warp staging
    __shared__ int s_is64;

    const int t = threadIdx.x;
    // W2 fragments for lane (g4,t4): rows {8k+t4, 8k+t4+4}, col 8n+g4 (cols>=30 zero)
    for (int i = t; i < 512; i += 128) {
        const int ln = i & 31, kn = i >> 5;
        const int k = kn >> 2, n = kn & 3;
        const int t4i = ln & 3, g = ln >> 2;
        const int col = 8 * n + g;
        const int r0 = 8 * k + t4i;
        const float v0 = (col < EOUT) ? W2[r0 * EOUT + col] : 0.0f;
        const float v1 = (col < EOUT) ? W2[(r0 + 4) * EOUT + col] : 0.0f;
        sW2x[i] = tf32_(v0);
        sW2y[i] = tf32_(v1);
    }
    // W3 fragments: rows >= 30 zero (k-dim pad)
    for (int i = t; i < 256; i += 128) {
        const int ln = i & 31, kn = i >> 5;
        const int k = kn >> 1, n = kn & 1;
        const int t4i = ln & 3, g = ln >> 2;
        const int col = 8 * n + g;
        const int r0 = 8 * k + t4i, r1 = r0 + 4;
        const float v0 = (r0 < EOUT) ? W3[r0 * 16 + col] : 0.0f;
        const float v1 = (r1 < EOUT) ? W3[r1 * 16 + col] : 0.0f;
        sW3x[i] = tf32_(v0);
        sW3y[i] = tf32_(v1);
    }
    if (t < 32) sW1L[t] = W1[32 * 32 + t];
    if (t < 32) sb2[t] = (t < EOUT) ? b2[t] : 0.0f;
    if (t == 0) {
        // int64 probe: little-endian int64 (<2^31) => odd int32 words are 0.
        s_is64 = (eidx[1] == 0 && eidx[3] == 0 && eidx[5] == 0 && eidx[7] == 0);
    }
    __syncthreads();

    const int wid  = t >> 5;
    const int lane = t & 31;
    const int g4   = lane >> 2;   // groupID (0..7)
    const int t4   = lane & 3;    // thread-in-group
    const int bsw  = g4 & 1;      // row-parity swizzle bit for h2 transpose
    const int e = e0 + blockIdx.x * 128 + t;
    const int b = blockIdx.y;

    int src, tgt;
    if (s_is64) {
        src = eidx[2 * (size_t)e];
        tgt = eidx[2 * ((size_t)EE + e)];
    } else {
        src = eidx[e];
        tgt = eidx[EE + e];
    }

    const float w = __ldg(ew + (size_t)b * EE + e);

    float* buf = stage[wid];
    const int chunk = lane & 7;   // which 16B chunk of a row
    const int sub   = lane >> 3;  // which of 4 rows this round

    // ---- stage A[src]+B[tgt] rows (coalesced; 8 lanes cover one 128B row) ----
    {
        const float* baseA = g_A + (size_t)b * NN * EH;
        const float* baseB = g_B + (size_t)b * NN * EH;
        #pragma unroll
        for (int i = 0; i < 8; i++) {
            const int eo = i * 4 + sub;                       // edge-in-warp
            const int rA = __shfl_sync(0xffffffffu, src, eo);
            const int rB = __shfl_sync(0xffffffffu, tgt, eo);
            float4 va = *(const float4*)(baseA + (size_t)rA * EH + chunk * 4);
            float4 vb = *(const float4*)(baseB + (size_t)rB * EH + chunk * 4);
            va.x += vb.x; va.y += vb.y; va.z += vb.z; va.w += vb.w;
            *(float4*)(buf + eo * SLOT_F + chunk * 4) = va;
        }
        __syncwarp();
    }

    // ---- fused layer 1 + A-fragment build (reads conflict-free: 4g4+8k+t4) ----
    float wr[4];
    #pragma unroll
    for (int i = 0; i < 4; i++) wr[i] = __shfl_sync(0xffffffffu, w, g4 + 8 * i);
    float wl[8];
    #pragma unroll
    for (int k = 0; k < 4; k++) {
        wl[2*k]   = sW1L[8*k + t4];
        wl[2*k+1] = sW1L[8*k + t4 + 4];
    }

    unsigned a[2][4][4];
    #pragma unroll
    for (int m = 0; m < 2; m++)
        #pragma unroll
        for (int k = 0; k < 4; k++) {
            const int rlo = (16*m + g4) * SLOT_F;
            const int rhi = (16*m + g4 + 8) * SLOT_F;
            a[m][k][0] = tf32_(sigmoid_fast(fmaf(wr[2*m],   wl[2*k],   buf[rlo + 8*k + t4])));
            a[m][k][1] = tf32_(sigmoid_fast(fmaf(wr[2*m+1], wl[2*k],   buf[rhi + 8*k + t4])));
            a[m][k][2] = tf32_(sigmoid_fast(fmaf(wr[2*m],   wl[2*k+1], buf[rlo + 8*k + t4 + 4])));
            a[m][k][3] = tf32_(sigmoid_fast(fmaf(wr[2*m+1], wl[2*k+1], buf[rhi + 8*k + t4 + 4])));
        }

    // ---- layer 2 on tensor cores: c = h1 @ W2 + b2 ----
    float c[2][4][4];
    #pragma unroll
    for (int m = 0; m < 2; m++)
        #pragma unroll
        for (int n = 0; n < 4; n++) {
            float v0 = sb2[8*n + 2*t4];
            float v1 = sb2[8*n + 2*t4 + 1];
            c[m][n][0] = v0; c[m][n][1] = v1; c[m][n][2] = v0; c[m][n][3] = v1;
        }
    #pragma unroll
    for (int k = 0; k < 4; k++)
        #pragma unroll
        for (int n = 0; n < 4; n++) {
            const unsigned bx = sW2x[(k * 4 + n) * 32 + lane];
            const unsigned by = sW2y[(k * 4 + n) * 32 + lane];
            #pragma unroll
            for (int m = 0; m < 2; m++)
                mma_tf32(c[m][n], a[m][k], bx, by);
        }

    // ---- sigmoid + transpose C-layout -> A-fragment layout ----
    // Row-parity XOR swizzle (pos = col ^ (row&1)), stride 36 (=4 mod 32):
    // both store and reload are conflict-free.
    __syncwarp();   // all staged-value reads done before overwrite
    unsigned* bufu = (unsigned*)buf;
    #pragma unroll
    for (int m = 0; m < 2; m++)
        #pragma unroll
        for (int n = 0; n < 4; n++) {
            const int base0 = (16*m + g4) * SLOT_F;
            const int base1 = (16*m + g4 + 8) * SLOT_F;
            const int cc = 8*n + 2*t4;
            bufu[base0 + cc + bsw]     = tf32_(sigmoid_fast(c[m][n][0]));
            bufu[base0 + cc + 1-bsw]   = tf32_(sigmoid_fast(c[m][n][1]));
            bufu[base1 + cc + bsw]     = tf32_(sigmoid_fast(c[m][n][2]));
            bufu[base1 + cc + 1-bsw]   = tf32_(sigmoid_fast(c[m][n][3]));
        }
    __syncwarp();
    {
        const int tlo = t4 ^ bsw;   // swizzled low bits for cols 8k+t4 / 8k+t4+4
        #pragma unroll
        for (int m = 0; m < 2; m++)
            #pragma unroll
            for (int k = 0; k < 4; k++) {
                const int rlo = (16*m + g4) * SLOT_F;
                const int rhi = (16*m + g4 + 8) * SLOT_F;
                a[m][k][0] = bufu[rlo + 8*k + tlo];
                a[m][k][1] = bufu[rhi + 8*k + tlo];
                a[m][k][2] = bufu[rlo + 8*k + 4 + tlo];
                a[m][k][3] = bufu[rhi + 8*k + 4 + tlo];
            }
    }

    // ---- layer 3 on tensor cores: d = h2 @ W3 (b3 folded in finalize) ----
    float d[2][2][4];
    #pragma unroll
    for (int m = 0; m < 2; m++)
        #pragma unroll
        for (int n = 0; n < 2; n++)
            d[m][n][0] = d[m][n][1] = d[m][n][2] = d[m][n][3] = 0.0f;
    #pragma unroll
    for (int k = 0; k < 4; k++)
        #pragma unroll
        for (int n = 0; n < 2; n++) {
            const unsigned bx = sW3x[(k * 2 + n) * 32 + lane];
            const unsigned by = sW3y[(k * 2 + n) * 32 + lane];
            #pragma unroll
            for (int m = 0; m < 2; m++)
                mma_tf32(d[m][n], a[m][k], bx, by);
        }

    // ---- scatter: regroup pairs into contiguous 16B chunks, red.v4 ----
    // Lane t4 holds cols {2t4,2t4+1} (P0) and {8+2t4,8+2t4+1} (P1) of row g4+8i.
    // Exchange with lane^1: even t4 keeps P0 + partner P0 -> cols 2t4..2t4+3;
    // odd t4 gets partner P1 + own P1 -> cols 6+2t4..9+2t4.
    #pragma unroll
    for (int i = 0; i < 4; i++) {
        const int m  = i >> 1;
        const int hi = (i & 1) * 2;
        const int row = g4 + 8 * i;          // rows: g4, g4+8, g4+16, g4+24
        const int rsrc = __shfl_sync(0xffffffffu, src, row);
        const int rtgt = __shfl_sync(0xffffffffu, tgt, row);
        const bool ev = (t4 & 1) == 0;
        const float s0 = ev ? d[m][1][hi]     : d[m][0][hi];
        const float s1 = ev ? d[m][1][hi + 1] : d[m][0][hi + 1];
        const float r0 = __shfl_xor_sync(0xffffffffu, s0, 1);
        const float r1 = __shfl_xor_sync(0xffffffffu, s1, 1);
        const float f0 = ev ? d[m][0][hi]     : r0;
        const float f1 = ev ? d[m][0][hi + 1] : r1;
        const float f2 = ev ? r0              : d[m][1][hi];
        const float f3 = ev ? r1              : d[m][1][hi + 1];
        const int off = ev ? (2 * t4) : (6 + 2 * t4);
        float* pt = out + ((size_t)b * NN + rtgt) * NOUT + off;
        float* ps = out + ((size_t)b * NN + rsrc) * NOUT + off;
        red_add4(pt,  f0,  f1,  f2,  f3);
        red_add4(ps, -f0, -f1, -f2, -f3);
    }
}

__global__ void finalize_kernel(float* __restrict__ out,
                                const float* __restrict__ b3, int n) {
    int i = blockIdx.x * blockDim.x + threadIdx.x;
    if (i < n) {
        float v = out[i] + __ldg(b3 + (i & 15));
        out[i] = sigmoidf_(v);
    }
}

extern "C" void kernel_launch(void* const* d_in, const int* in_sizes, int n_in,
                              void* d_out, int out_size) {
    const float* nf   = (const float*)d_in[0];      // node_features (B,N,F)
    const float* ew   = (const float*)d_in[1];      // edge_weight   (B,E)
    const int*   eidx = (const int*)d_in[2];        // edge_index    (2,E)
    const float* W1   = (const float*)d_in[3];
    const float* b1   = (const float*)d_in[4];
    const float* W2   = (const float*)d_in[5];
    const float* b2   = (const float*)d_in[6];
    const float* W3   = (const float*)d_in[7];
    const float* b3   = (const float*)d_in[8];
    float* out = (float*)d_out;

    const int total = BB * NN * NOUT;  // 1,600,000 floats
    const int n4 = total / 4;

    zero_kernel<<<(n4 + 255) / 256, 256>>>((float4*)out, n4);
    node_kernel<<<(BB * NN + 127) / 128, 128>>>(nf, W1, b1);

    // Edge work split in two launches (also aligns ncu's -s 5 onto edge_kernel).
    dim3 grid((EE / 2) / 128, BB);   // EE % 256 == 0 -> all warps full
    edge_kernel<<<grid, 128>>>(ew, eidx, W1, W2, b2, W3, out, 0);
    edge_kernel<<<grid, 128>>>(ew, eidx, W1, W2, b2, W3, out, EE / 2);

    finalize_kernel<<<(total + 255) / 256, 256>>>(out, b3, total);
}